// round 6
// baseline (speedup 1.0000x reference)
#include <cuda_runtime.h>
#include <cuda_bf16.h>
#include <stdint.h>

#define DIMC 768
#define NH 12
#define HD 64
#define BSZ 2
#define TLEN 2048
#define MROWS 4096

// ---------------- scratch ----------------
__device__ __nv_bfloat16 g_xq_hi[MROWS * DIMC], g_xq_lo[MROWS * DIMC];  // split inputs
__device__ __nv_bfloat16 g_xk_hi[MROWS * DIMC], g_xk_lo[MROWS * DIMC];
__device__ __nv_bfloat16 g_xv_hi[MROWS * DIMC], g_xv_lo[MROWS * DIMC];
__device__ __nv_bfloat16 g_wq_hi[DIMC * DIMC], g_wq_lo[DIMC * DIMC];    // split weights
__device__ __nv_bfloat16 g_wk_hi[DIMC * DIMC], g_wk_lo[DIMC * DIMC];
__device__ __nv_bfloat16 g_wv_hi[DIMC * DIMC], g_wv_lo[DIMC * DIMC];
__device__ __nv_bfloat16 g_wo_hi[DIMC * DIMC], g_wo_lo[DIMC * DIMC];
__device__ __nv_bfloat16 g_q_hi[MROWS * DIMC], g_q_lo[MROWS * DIMC];    // [b,h,t,d]
__device__ __nv_bfloat16 g_k_hi[MROWS * DIMC], g_k_lo[MROWS * DIMC];
__device__ __nv_bfloat16 g_v_hi[MROWS * DIMC], g_v_lo[MROWS * DIMC];
__device__ __nv_bfloat16 g_a_hi[MROWS * DIMC], g_a_lo[MROWS * DIMC];    // attn out [b,t,c]

// ---------------- helpers ----------------
__device__ __forceinline__ uint32_t smem_u32(const void* p) {
    uint32_t a;
    asm("{ .reg .u64 t; cvta.to.shared.u64 t, %1; cvt.u32.u64 %0, t; }" : "=r"(a) : "l"(p));
    return a;
}
__device__ __forceinline__ void cp16(uint32_t dst, const void* src) {
    asm volatile("cp.async.cg.shared.global [%0], [%1], 16;" :: "r"(dst), "l"(src) : "memory");
}
#define CP_COMMIT() asm volatile("cp.async.commit_group;" ::: "memory")
#define CP_WAIT0()  asm volatile("cp.async.wait_group 0;" ::: "memory")
#define CP_WAIT1()  asm volatile("cp.async.wait_group 1;" ::: "memory")
__device__ __forceinline__ void ldm4(uint32_t* r, uint32_t addr) {
    asm volatile("ldmatrix.sync.aligned.m8n8.x4.shared.b16 {%0,%1,%2,%3}, [%4];"
        : "=r"(r[0]), "=r"(r[1]), "=r"(r[2]), "=r"(r[3]) : "r"(addr));
}
__device__ __forceinline__ void ldm4t(uint32_t* r, uint32_t addr) {
    asm volatile("ldmatrix.sync.aligned.m8n8.x4.trans.shared.b16 {%0,%1,%2,%3}, [%4];"
        : "=r"(r[0]), "=r"(r[1]), "=r"(r[2]), "=r"(r[3]) : "r"(addr));
}
__device__ __forceinline__ void mma16816(float* c, const uint32_t* a, uint32_t b0, uint32_t b1) {
    asm volatile("mma.sync.aligned.m16n8k16.row.col.f32.bf16.bf16.f32 "
        "{%0,%1,%2,%3}, {%4,%5,%6,%7}, {%8,%9}, {%0,%1,%2,%3};"
        : "+f"(c[0]), "+f"(c[1]), "+f"(c[2]), "+f"(c[3])
        : "r"(a[0]), "r"(a[1]), "r"(a[2]), "r"(a[3]), "r"(b0), "r"(b1));
}
__device__ __forceinline__ uint32_t pack_hi(float x, float y) {
    __nv_bfloat162 h;
    h.x = __float2bfloat16(x);
    h.y = __float2bfloat16(y);
    return *(uint32_t*)&h;
}
__device__ __forceinline__ uint32_t pack_lo(float x, float y, uint32_t hi) {
    __nv_bfloat162 h = *(__nv_bfloat162*)&hi;
    __nv_bfloat162 l;
    l.x = __float2bfloat16(x - __bfloat162float(h.x));
    l.y = __float2bfloat16(y - __bfloat162float(h.y));
    return *(uint32_t*)&l;
}

#define SW128(o) ((uint32_t)(o) ^ ((((uint32_t)(o)) >> 3) & 0x70))

// ====================== split kernels =======================================
__device__ __forceinline__ void split4(const float* src, __nv_bfloat16* hi,
                                       __nv_bfloat16* lo, int i) {
    float4 v = ((const float4*)src)[i];
    uint32_t h0 = pack_hi(v.x, v.y), h1 = pack_hi(v.z, v.w);
    uint32_t l0 = pack_lo(v.x, v.y, h0), l1 = pack_lo(v.z, v.w, h1);
    uint2 hh = {h0, h1}, ll = {l0, l1};
    ((uint2*)hi)[i] = hh;
    ((uint2*)lo)[i] = ll;
}

__global__ __launch_bounds__(256)
void split_in_kernel(const float* __restrict__ s0, const float* __restrict__ s1,
                     const float* __restrict__ s2,
                     __nv_bfloat16* h0, __nv_bfloat16* l0,
                     __nv_bfloat16* h1, __nv_bfloat16* l1,
                     __nv_bfloat16* h2, __nv_bfloat16* l2) {
    int z = blockIdx.y;
    const float* s = z == 0 ? s0 : z == 1 ? s1 : s2;
    __nv_bfloat16* h = z == 0 ? h0 : z == 1 ? h1 : h2;
    __nv_bfloat16* l = z == 0 ? l0 : z == 1 ? l1 : l2;
    int i = blockIdx.x * 256 + threadIdx.x;
    split4(s, h, l, i);
}

__global__ __launch_bounds__(256)
void split_w_kernel(const float* __restrict__ s0, const float* __restrict__ s1,
                    const float* __restrict__ s2, const float* __restrict__ s3,
                    __nv_bfloat16* h0, __nv_bfloat16* l0,
                    __nv_bfloat16* h1, __nv_bfloat16* l1,
                    __nv_bfloat16* h2, __nv_bfloat16* l2,
                    __nv_bfloat16* h3, __nv_bfloat16* l3) {
    int z = blockIdx.y;
    const float* s = z == 0 ? s0 : z == 1 ? s1 : z == 2 ? s2 : s3;
    __nv_bfloat16* h = z == 0 ? h0 : z == 1 ? h1 : z == 2 ? h2 : h3;
    __nv_bfloat16* l = z == 0 ? l0 : z == 1 ? l1 : z == 2 ? l2 : l3;
    int i = blockIdx.x * 256 + threadIdx.x;
    split4(s, h, l, i);
}

// ====================== projection GEMM (3-stage cp.async ring) =============
// C[M,N] = A @ W^T + bias. 128x128 tiles, BK=32, 3 stages, 1 sync per chunk.
#define PTILE 10240            // 128 rows x 80 B
#define PSTG  40960            // 4 tiles (Ah, Al, Wh, Wl)
#define PSMEM (3 * PSTG)       // 122880

__device__ __forceinline__ void proj_issue(
    uint32_t stg, const __nv_bfloat16* ah, const __nv_bfloat16* al,
    const __nv_bfloat16* wh, const __nv_bfloat16* wl,
    int row0, int col0, int k0, int tid) {
#pragma unroll
    for (int j = 0; j < 2; j++) {
        int idx = tid + j * 256;              // 0..511
        int r = idx >> 2, ch = idx & 3;
        uint32_t doff = (uint32_t)(r * 80 + ch * 16);
        size_t ga = (size_t)(row0 + r) * DIMC + k0 + ch * 8;
        size_t gw = (size_t)(col0 + r) * DIMC + k0 + ch * 8;
        cp16(stg + doff,             ah + ga);
        cp16(stg + PTILE + doff,     al + ga);
        cp16(stg + 2 * PTILE + doff, wh + gw);
        cp16(stg + 3 * PTILE + doff, wl + gw);
    }
}

template <int MODE>
__global__ __launch_bounds__(256, 1)
void proj_kernel(
    const __nv_bfloat16* a0h, const __nv_bfloat16* a0l,
    const __nv_bfloat16* a1h, const __nv_bfloat16* a1l,
    const __nv_bfloat16* a2h, const __nv_bfloat16* a2l,
    const __nv_bfloat16* w0h, const __nv_bfloat16* w0l,
    const __nv_bfloat16* w1h, const __nv_bfloat16* w1l,
    const __nv_bfloat16* w2h, const __nv_bfloat16* w2l,
    const float* b0, const float* b1, const float* b2,
    __nv_bfloat16* o0h, __nv_bfloat16* o0l,
    __nv_bfloat16* o1h, __nv_bfloat16* o1l,
    __nv_bfloat16* o2h, __nv_bfloat16* o2l,
    float* of32) {
    extern __shared__ __align__(16) char dsm[];
    const uint32_t sb = smem_u32(dsm);
    const int tid = threadIdx.x;
    const int wid = tid >> 5;
    const int lane = tid & 31;
    const int wm = wid >> 2;
    const int wn = wid & 3;
    const int row0 = blockIdx.x * 128;
    const int col0 = blockIdx.y * 128;
    const int z = blockIdx.z;

    const __nv_bfloat16* ah = z == 0 ? a0h : z == 1 ? a1h : a2h;
    const __nv_bfloat16* al = z == 0 ? a0l : z == 1 ? a1l : a2l;
    const __nv_bfloat16* wh = z == 0 ? w0h : z == 1 ? w1h : w2h;
    const __nv_bfloat16* wl = z == 0 ? w0l : z == 1 ? w1l : w2l;
    const float* bias       = z == 0 ? b0 : z == 1 ? b1 : b2;
    __nv_bfloat16* ohp      = z == 0 ? o0h : z == 1 ? o1h : o2h;
    __nv_bfloat16* olp      = z == 0 ? o0l : z == 1 ? o1l : o2l;

    float bias_r[4][2];
#pragma unroll
    for (int j = 0; j < 4; j++) {
        int c = col0 + wn * 32 + j * 8 + (lane & 3) * 2;
        float2 bv = *(const float2*)&bias[c];
        bias_r[j][0] = bv.x;
        bias_r[j][1] = bv.y;
    }

    float acc[4][4][4];
#pragma unroll
    for (int i = 0; i < 4; i++)
#pragma unroll
        for (int j = 0; j < 4; j++)
#pragma unroll
            for (int k = 0; k < 4; k++) acc[i][j][k] = 0.f;

    const int lrow_a = (lane & 7) + (lane & 8);
    const int lcb = (lane >> 4) * 16;

    proj_issue(sb, ah, al, wh, wl, row0, col0, 0, tid);
    CP_COMMIT();
    proj_issue(sb + PSTG, ah, al, wh, wl, row0, col0, 32, tid);
    CP_COMMIT();

    for (int kt = 0; kt < 24; kt++) {
        if (kt < 23) { CP_WAIT1(); } else { CP_WAIT0(); }
        __syncthreads();
        if (kt < 22) {
            proj_issue(sb + ((kt + 2) % 3) * PSTG, ah, al, wh, wl, row0, col0, (kt + 2) * 32, tid);
            CP_COMMIT();
        }
        const uint32_t stg = sb + (kt % 3) * PSTG;
        const uint32_t sA_h = stg, sA_l = stg + PTILE, sW_h = stg + 2 * PTILE, sW_l = stg + 3 * PTILE;
#pragma unroll
        for (int ks = 0; ks < 2; ks++) {
            const uint32_t kb = (uint32_t)(ks * 32 + lcb);
            uint32_t ahf[4][4], alf[4][4];
#pragma unroll
            for (int i = 0; i < 4; i++) {
                uint32_t off = (uint32_t)((wm * 64 + i * 16 + lrow_a) * 80) + kb;
                ldm4(ahf[i], sA_h + off);
                ldm4(alf[i], sA_l + off);
            }
#pragma unroll
            for (int g = 0; g < 2; g++) {
                uint32_t off = (uint32_t)((wn * 32 + g * 16 + lrow_a) * 80) + kb;
                uint32_t bh4[4], bl4[4];
                ldm4(bh4, sW_h + off);
                ldm4(bl4, sW_l + off);
#pragma unroll
                for (int i = 0; i < 4; i++) {
                    mma16816(acc[i][2 * g],     ahf[i], bh4[0], bh4[2]);
                    mma16816(acc[i][2 * g],     ahf[i], bl4[0], bl4[2]);
                    mma16816(acc[i][2 * g],     alf[i], bh4[0], bh4[2]);
                    mma16816(acc[i][2 * g + 1], ahf[i], bh4[1], bh4[3]);
                    mma16816(acc[i][2 * g + 1], ahf[i], bl4[1], bl4[3]);
                    mma16816(acc[i][2 * g + 1], alf[i], bh4[1], bh4[3]);
                }
            }
        }
    }

    // epilogue
#pragma unroll
    for (int i = 0; i < 4; i++) {
        const int m0 = row0 + wm * 64 + i * 16 + (lane >> 2);
#pragma unroll
        for (int j = 0; j < 4; j++) {
            const int c = col0 + wn * 32 + j * 8 + (lane & 3) * 2;
            float v0 = acc[i][j][0] + bias_r[j][0];
            float v1 = acc[i][j][1] + bias_r[j][1];
            float v2 = acc[i][j][2] + bias_r[j][0];
            float v3 = acc[i][j][3] + bias_r[j][1];
            if (MODE == 0) {
                const int h = c >> 6, d = c & 63;
                {
                    const int gr = m0, b = gr >> 11, t = gr & 2047;
                    size_t oi = (((size_t)b * NH + h) * TLEN + t) * HD + d;
                    uint32_t hh = pack_hi(v0, v1);
                    *(uint32_t*)&ohp[oi] = hh;
                    *(uint32_t*)&olp[oi] = pack_lo(v0, v1, hh);
                }
                {
                    const int gr = m0 + 8, b = gr >> 11, t = gr & 2047;
                    size_t oi = (((size_t)b * NH + h) * TLEN + t) * HD + d;
                    uint32_t hh = pack_hi(v2, v3);
                    *(uint32_t*)&ohp[oi] = hh;
                    *(uint32_t*)&olp[oi] = pack_lo(v2, v3, hh);
                }
            } else {
                float2 r01 = {v0, v1}, r23 = {v2, v3};
                *(float2*)&of32[(size_t)m0 * DIMC + c] = r01;
                *(float2*)&of32[(size_t)(m0 + 8) * DIMC + c] = r23;
            }
        }
    }
}

// ====================== attention: 64q CTAs, occ 2, 3-stage ring ============
// CTA: 64 queries, 128 threads (4 warps x 16 rows). KV tiles 64 rows.
// stage = KH | KL | VH | VL, each 64x128B = 8KB -> 32KB; 3 stages = 96KB.
#define ATILE 8192
#define ASTG  32768
#define AT_SMEM (3 * ASTG)     // 98304

__device__ __forceinline__ void attn_issue_tile(
    uint32_t tilebase, const __nv_bfloat16* src, int tid) {
#pragma unroll
    for (int j = 0; j < 4; j++) {
        int idx = tid + j * 128;     // 0..511 (64 rows x 8 chunks)
        int r = idx >> 3, ch = idx & 7;
        cp16(tilebase + SW128(r * 128 + ch * 16), src + (size_t)r * HD + ch * 8);
    }
}
__device__ __forceinline__ void attn_issue_stage(
    uint32_t stg, const __nv_bfloat16* Kh, const __nv_bfloat16* Kl,
    const __nv_bfloat16* Vh, const __nv_bfloat16* Vl, size_t off, int tid) {
    attn_issue_tile(stg,             Kh + off, tid);
    attn_issue_tile(stg + ATILE,     Kl + off, tid);
    attn_issue_tile(stg + 2 * ATILE, Vh + off, tid);
    attn_issue_tile(stg + 3 * ATILE, Vl + off, tid);
}

__global__ __launch_bounds__(128, 2)
void attn_kernel(const __nv_bfloat16* __restrict__ qh, const __nv_bfloat16* __restrict__ ql,
                 const __nv_bfloat16* __restrict__ kh, const __nv_bfloat16* __restrict__ kl,
                 const __nv_bfloat16* __restrict__ vh, const __nv_bfloat16* __restrict__ vl,
                 __nv_bfloat16* __restrict__ o_hi, __nv_bfloat16* __restrict__ o_lo) {
    extern __shared__ __align__(16) char dsm[];
    const uint32_t sb = smem_u32(dsm);
    const int tid = threadIdx.x;
    const int w = tid >> 5;
    const int lane = tid & 31;
    const int bh = blockIdx.y;
    const int q0 = blockIdx.x * 64;

    const __nv_bfloat16* Qh = qh + ((size_t)bh * TLEN + q0) * HD;
    const __nv_bfloat16* Ql = ql + ((size_t)bh * TLEN + q0) * HD;
    const __nv_bfloat16* Kh = kh + (size_t)bh * TLEN * HD;
    const __nv_bfloat16* Kl = kl + (size_t)bh * TLEN * HD;
    const __nv_bfloat16* Vh = vh + (size_t)bh * TLEN * HD;
    const __nv_bfloat16* Vl = vl + (size_t)bh * TLEN * HD;

    // prologue: stage Q through stage0, extract fragments
    attn_issue_tile(sb, Qh, tid);
    attn_issue_tile(sb + ATILE, Ql, tid);
    CP_COMMIT();
    CP_WAIT0();
    __syncthreads();

    const int lrow = (lane & 7) + (lane & 8);
    const int lcb = (lane >> 4) * 16;
    uint32_t qah[4][4], qal[4][4];
#pragma unroll
    for (int ks = 0; ks < 4; ks++) {
        uint32_t so = SW128((w * 16 + lrow) * 128 + ks * 32 + lcb);
        ldm4(qah[ks], sb + so);
        ldm4(qal[ks], sb + ATILE + so);
    }
    __syncthreads();

    // issue KV tiles 0,1
    attn_issue_stage(sb, Kh, Kl, Vh, Vl, 0, tid);
    CP_COMMIT();
    attn_issue_stage(sb + ASTG, Kh, Kl, Vh, Vl, (size_t)64 * HD, tid);
    CP_COMMIT();

    float oacc[8][4];
#pragma unroll
    for (int j = 0; j < 8; j++)
#pragma unroll
        for (int k = 0; k < 4; k++) oacc[j][k] = 0.f;
    float lsum0 = 0.f, lsum1 = 0.f;

    for (int t = 0; t < 32; t++) {
        if (t < 31) { CP_WAIT1(); } else { CP_WAIT0(); }
        __syncthreads();
        if (t < 30) {
            attn_issue_stage(sb + ((t + 2) % 3) * ASTG, Kh, Kl, Vh, Vl,
                             (size_t)(t + 2) * 64 * HD, tid);
            CP_COMMIT();
        }
        const uint32_t cb = sb + (t % 3) * ASTG;
        const uint32_t cKH = cb, cKL = cb + ATILE, cVH = cb + 2 * ATILE, cVL = cb + 3 * ATILE;

        // S = Q K^T : 16 x 64 per warp
        float sc[8][4];
#pragma unroll
        for (int j = 0; j < 8; j++)
#pragma unroll
            for (int k = 0; k < 4; k++) sc[j][k] = 0.f;
#pragma unroll
        for (int ks = 0; ks < 4; ks++) {
            const uint32_t kb = (uint32_t)(ks * 32 + lcb);
#pragma unroll
            for (int g = 0; g < 4; g++) {
                uint32_t so = SW128((g * 16 + lrow) * 128 + kb);
                uint32_t bh4[4], bl4[4];
                ldm4(bh4, cKH + so);
                ldm4(bl4, cKL + so);
                mma16816(sc[2 * g],     qah[ks], bh4[0], bh4[2]);
                mma16816(sc[2 * g],     qah[ks], bl4[0], bl4[2]);
                mma16816(sc[2 * g],     qal[ks], bh4[0], bh4[2]);
                mma16816(sc[2 * g + 1], qah[ks], bh4[1], bh4[3]);
                mma16816(sc[2 * g + 1], qah[ks], bl4[1], bl4[3]);
                mma16816(sc[2 * g + 1], qal[ks], bh4[1], bh4[3]);
            }
        }

        // softmax (bounded scores, no max subtraction) + pack P hi/lo
        uint32_t ph[8][2], pl[8][2];
        float p0 = 0.f, p1 = 0.f;
#pragma unroll
        for (int j = 0; j < 8; j++) {
            float e0 = __expf(sc[j][0] * 0.125f);
            float e1 = __expf(sc[j][1] * 0.125f);
            float e2 = __expf(sc[j][2] * 0.125f);
            float e3 = __expf(sc[j][3] * 0.125f);
            p0 += e0 + e1;
            p1 += e2 + e3;
            ph[j][0] = pack_hi(e0, e1);
            pl[j][0] = pack_lo(e0, e1, ph[j][0]);
            ph[j][1] = pack_hi(e2, e3);
            pl[j][1] = pack_lo(e2, e3, ph[j][1]);
        }
        lsum0 += p0;
        lsum1 += p1;

        // O += P V : P [16 x 64], V [64 x 64]
#pragma unroll
        for (int ks2 = 0; ks2 < 4; ks2++) {
            uint32_t pah[4] = {ph[2 * ks2][0], ph[2 * ks2][1], ph[2 * ks2 + 1][0], ph[2 * ks2 + 1][1]};
            uint32_t pal[4] = {pl[2 * ks2][0], pl[2 * ks2][1], pl[2 * ks2 + 1][0], pl[2 * ks2 + 1][1]};
#pragma unroll
            for (int g = 0; g < 4; g++) {
                uint32_t so = SW128((ks2 * 16 + lrow) * 128 + g * 32 + lcb);
                uint32_t vhf[4], vlf[4];
                ldm4t(vhf, cVH + so);
                ldm4t(vlf, cVL + so);
                mma16816(oacc[2 * g],     pah, vhf[0], vhf[1]);
                mma16816(oacc[2 * g],     pah, vlf[0], vlf[1]);
                mma16816(oacc[2 * g],     pal, vhf[0], vhf[1]);
                mma16816(oacc[2 * g + 1], pah, vhf[2], vhf[3]);
                mma16816(oacc[2 * g + 1], pah, vlf[2], vlf[3]);
                mma16816(oacc[2 * g + 1], pal, vhf[2], vhf[3]);
            }
        }
    }

    lsum0 += __shfl_xor_sync(0xffffffffu, lsum0, 1);
    lsum0 += __shfl_xor_sync(0xffffffffu, lsum0, 2);
    lsum1 += __shfl_xor_sync(0xffffffffu, lsum1, 1);
    lsum1 += __shfl_xor_sync(0xffffffffu, lsum1, 2);
    const float inv0 = 1.f / lsum0;
    const float inv1 = 1.f / lsum1;

    const int b = bh / NH, h = bh % NH;
    const int qr0 = q0 + w * 16 + (lane >> 2);
    const int qr1 = qr0 + 8;
    size_t base0 = ((size_t)b * TLEN + qr0) * DIMC + h * HD + (lane & 3) * 2;
    size_t base1 = ((size_t)b * TLEN + qr1) * DIMC + h * HD + (lane & 3) * 2;
#pragma unroll
    for (int g = 0; g < 8; g++) {
        float x0 = oacc[g][0] * inv0, y0 = oacc[g][1] * inv0;
        float x1 = oacc[g][2] * inv1, y1 = oacc[g][3] * inv1;
        uint32_t h0 = pack_hi(x0, y0), h1 = pack_hi(x1, y1);
        *(uint32_t*)&o_hi[base0 + g * 8] = h0;
        *(uint32_t*)&o_lo[base0 + g * 8] = pack_lo(x0, y0, h0);
        *(uint32_t*)&o_hi[base1 + g * 8] = h1;
        *(uint32_t*)&o_lo[base1 + g * 8] = pack_lo(x1, y1, h1);
    }
}

// ====================== launch ==============================================
extern "C" void kernel_launch(void* const* d_in, const int* in_sizes, int n_in,
                              void* d_out, int out_size) {
    const float* q_in = (const float*)d_in[0];
    const float* k_in = (const float*)d_in[1];
    const float* v_in = (const float*)d_in[2];
    const float* Wq = (const float*)d_in[3];
    const float* bq = (const float*)d_in[4];
    const float* Wk = (const float*)d_in[5];
    const float* bk = (const float*)d_in[6];
    const float* Wv = (const float*)d_in[7];
    const float* bv = (const float*)d_in[8];
    const float* Wo = (const float*)d_in[9];
    const float* bo = (const float*)d_in[10];
    float* out = (float*)d_out;

    __nv_bfloat16 *xqh, *xql, *xkh, *xkl, *xvh, *xvl;
    __nv_bfloat16 *wqh, *wql, *wkh, *wkl, *wvh, *wvl, *woh, *wol;
    __nv_bfloat16 *pqh, *pql, *pkh, *pkl, *pvh, *pvl, *pah, *pal;
    cudaGetSymbolAddress((void**)&xqh, g_xq_hi); cudaGetSymbolAddress((void**)&xql, g_xq_lo);
    cudaGetSymbolAddress((void**)&xkh, g_xk_hi); cudaGetSymbolAddress((void**)&xkl, g_xk_lo);
    cudaGetSymbolAddress((void**)&xvh, g_xv_hi); cudaGetSymbolAddress((void**)&xvl, g_xv_lo);
    cudaGetSymbolAddress((void**)&wqh, g_wq_hi); cudaGetSymbolAddress((void**)&wql, g_wq_lo);
    cudaGetSymbolAddress((void**)&wkh, g_wk_hi); cudaGetSymbolAddress((void**)&wkl, g_wk_lo);
    cudaGetSymbolAddress((void**)&wvh, g_wv_hi); cudaGetSymbolAddress((void**)&wvl, g_wv_lo);
    cudaGetSymbolAddress((void**)&woh, g_wo_hi); cudaGetSymbolAddress((void**)&wol, g_wo_lo);
    cudaGetSymbolAddress((void**)&pqh, g_q_hi);  cudaGetSymbolAddress((void**)&pql, g_q_lo);
    cudaGetSymbolAddress((void**)&pkh, g_k_hi);  cudaGetSymbolAddress((void**)&pkl, g_k_lo);
    cudaGetSymbolAddress((void**)&pvh, g_v_hi);  cudaGetSymbolAddress((void**)&pvl, g_v_lo);
    cudaGetSymbolAddress((void**)&pah, g_a_hi);  cudaGetSymbolAddress((void**)&pal, g_a_lo);

    cudaFuncSetAttribute(proj_kernel<0>, cudaFuncAttributeMaxDynamicSharedMemorySize, PSMEM);
    cudaFuncSetAttribute(proj_kernel<1>, cudaFuncAttributeMaxDynamicSharedMemorySize, PSMEM);
    cudaFuncSetAttribute(attn_kernel, cudaFuncAttributeMaxDynamicSharedMemorySize, AT_SMEM);

    // splits
    dim3 sig(MROWS * DIMC / 4 / 256, 3);
    split_in_kernel<<<sig, 256>>>(q_in, k_in, v_in, xqh, xql, xkh, xkl, xvh, xvl);
    dim3 swg(DIMC * DIMC / 4 / 256, 4);
    split_w_kernel<<<swg, 256>>>(Wq, Wk, Wv, Wo, wqh, wql, wkh, wkl, wvh, wvl, woh, wol);

    // fused QKV projection
    dim3 pgrid(MROWS / 128, DIMC / 128, 3);   // 32 x 6 x 3 = 576 CTAs
    proj_kernel<0><<<pgrid, 256, PSMEM>>>(
        xqh, xql, xkh, xkl, xvh, xvl,
        wqh, wql, wkh, wkl, wvh, wvl,
        bq, bk, bv,
        pqh, pql, pkh, pkl, pvh, pvl,
        nullptr);

    dim3 agrid(TLEN / 64, BSZ * NH);           // 32 x 24 = 768 CTAs
    attn_kernel<<<agrid, 128, AT_SMEM>>>(pqh, pql, pkh, pkl, pvh, pvl, pah, pal);

    // O projection
    dim3 ogrid(MROWS / 128, DIMC / 128, 1);
    proj_kernel<1><<<ogrid, 256, PSMEM>>>(
        pah, pal, nullptr, nullptr, nullptr, nullptr,
        woh, wol, nullptr, nullptr, nullptr, nullptr,
        bo, nullptr, nullptr,
        nullptr, nullptr, nullptr, nullptr, nullptr, nullptr,
        out);
}

// round 7
// speedup vs baseline: 1.1163x; 1.1163x over previous
#include <cuda_runtime.h>
#include <cuda_bf16.h>
#include <cuda_fp16.h>
#include <stdint.h>

#define DIMC 768
#define NH 12
#define HD 64
#define BSZ 2
#define TLEN 2048
#define MROWS 4096

// ---------------- scratch ----------------
__device__ __half g_xq[MROWS * DIMC];                       // fp16 inputs (Q,K paths)
__device__ __half g_xk[MROWS * DIMC];
__device__ __half g_xv_h[MROWS * DIMC], g_xv_l[MROWS * DIMC];  // V input split fp16
__device__ __half g_wq[DIMC * DIMC], g_wk[DIMC * DIMC], g_wv[DIMC * DIMC];  // fp16 weights
__device__ __nv_bfloat16 g_wo_hi[DIMC * DIMC], g_wo_lo[DIMC * DIMC];        // Wo bf16 split
__device__ __half g_q[MROWS * DIMC], g_k[MROWS * DIMC], g_v[MROWS * DIMC];  // [b,h,t,d] fp16
__device__ __nv_bfloat16 g_a_hi[MROWS * DIMC], g_a_lo[MROWS * DIMC];        // attn out [b,t,c]

// ---------------- helpers ----------------
__device__ __forceinline__ uint32_t smem_u32(const void* p) {
    uint32_t a;
    asm("{ .reg .u64 t; cvta.to.shared.u64 t, %1; cvt.u32.u64 %0, t; }" : "=r"(a) : "l"(p));
    return a;
}
__device__ __forceinline__ void cp16(uint32_t dst, const void* src) {
    asm volatile("cp.async.cg.shared.global [%0], [%1], 16;" :: "r"(dst), "l"(src) : "memory");
}
#define CP_COMMIT() asm volatile("cp.async.commit_group;" ::: "memory")
#define CP_WAIT0()  asm volatile("cp.async.wait_group 0;" ::: "memory")
#define CP_WAIT1()  asm volatile("cp.async.wait_group 1;" ::: "memory")
__device__ __forceinline__ void ldm4(uint32_t* r, uint32_t addr) {
    asm volatile("ldmatrix.sync.aligned.m8n8.x4.shared.b16 {%0,%1,%2,%3}, [%4];"
        : "=r"(r[0]), "=r"(r[1]), "=r"(r[2]), "=r"(r[3]) : "r"(addr));
}
__device__ __forceinline__ void ldm4t(uint32_t* r, uint32_t addr) {
    asm volatile("ldmatrix.sync.aligned.m8n8.x4.trans.shared.b16 {%0,%1,%2,%3}, [%4];"
        : "=r"(r[0]), "=r"(r[1]), "=r"(r[2]), "=r"(r[3]) : "r"(addr));
}
// bf16 mma (kept for O projection)
__device__ __forceinline__ void mma_bf16(float* c, const uint32_t* a, uint32_t b0, uint32_t b1) {
    asm volatile("mma.sync.aligned.m16n8k16.row.col.f32.bf16.bf16.f32 "
        "{%0,%1,%2,%3}, {%4,%5,%6,%7}, {%8,%9}, {%0,%1,%2,%3};"
        : "+f"(c[0]), "+f"(c[1]), "+f"(c[2]), "+f"(c[3])
        : "r"(a[0]), "r"(a[1]), "r"(a[2]), "r"(a[3]), "r"(b0), "r"(b1));
}
// fp16 mma
__device__ __forceinline__ void mma_f16(float* c, const uint32_t* a, uint32_t b0, uint32_t b1) {
    asm volatile("mma.sync.aligned.m16n8k16.row.col.f32.f16.f16.f32 "
        "{%0,%1,%2,%3}, {%4,%5,%6,%7}, {%8,%9}, {%0,%1,%2,%3};"
        : "+f"(c[0]), "+f"(c[1]), "+f"(c[2]), "+f"(c[3])
        : "r"(a[0]), "r"(a[1]), "r"(a[2]), "r"(a[3]), "r"(b0), "r"(b1));
}
__device__ __forceinline__ uint32_t packh(float x, float y) {
    __half2 h = __floats2half2_rn(x, y);
    return *(uint32_t*)&h;
}
__device__ __forceinline__ uint32_t pack_bhi(float x, float y) {
    __nv_bfloat162 h;
    h.x = __float2bfloat16(x);
    h.y = __float2bfloat16(y);
    return *(uint32_t*)&h;
}
__device__ __forceinline__ uint32_t pack_blo(float x, float y, uint32_t hi) {
    __nv_bfloat162 h = *(__nv_bfloat162*)&hi;
    __nv_bfloat162 l;
    l.x = __float2bfloat16(x - __bfloat162float(h.x));
    l.y = __float2bfloat16(y - __bfloat162float(h.y));
    return *(uint32_t*)&l;
}

#define SW128(o) ((uint32_t)(o) ^ ((((uint32_t)(o)) >> 3) & 0x70))

// ====================== split kernels =======================================
// inputs: z0 -> q fp16, z1 -> k fp16, z2 -> v fp16 hi+lo
__global__ __launch_bounds__(256)
void split_x_kernel(const float* __restrict__ s0, const float* __restrict__ s1,
                    const float* __restrict__ s2,
                    __half* xq, __half* xk, __half* xvh, __half* xvl) {
    int z = blockIdx.y;
    int i = blockIdx.x * 256 + threadIdx.x;
    const float* s = z == 0 ? s0 : z == 1 ? s1 : s2;
    float4 v = ((const float4*)s)[i];
    if (z < 2) {
        __half* d = z == 0 ? xq : xk;
        uint2 o = {packh(v.x, v.y), packh(v.z, v.w)};
        ((uint2*)d)[i] = o;
    } else {
        uint32_t h0 = packh(v.x, v.y), h1 = packh(v.z, v.w);
        __half2 a = *(__half2*)&h0, b = *(__half2*)&h1;
        uint32_t l0 = packh(v.x - __half2float(a.x), v.y - __half2float(a.y));
        uint32_t l1 = packh(v.z - __half2float(b.x), v.w - __half2float(b.y));
        uint2 hh = {h0, h1}, ll = {l0, l1};
        ((uint2*)xvh)[i] = hh;
        ((uint2*)xvl)[i] = ll;
    }
}

// weights: z0..2 -> Wq/Wk/Wv fp16;  z3 -> Wo bf16 hi/lo
__global__ __launch_bounds__(256)
void split_w_kernel(const float* __restrict__ s0, const float* __restrict__ s1,
                    const float* __restrict__ s2, const float* __restrict__ s3,
                    __half* wq, __half* wk, __half* wv,
                    __nv_bfloat16* woh, __nv_bfloat16* wol) {
    int z = blockIdx.y;
    int i = blockIdx.x * 256 + threadIdx.x;
    const float* s = z == 0 ? s0 : z == 1 ? s1 : z == 2 ? s2 : s3;
    float4 v = ((const float4*)s)[i];
    if (z < 3) {
        __half* d = z == 0 ? wq : z == 1 ? wk : wv;
        uint2 o = {packh(v.x, v.y), packh(v.z, v.w)};
        ((uint2*)d)[i] = o;
    } else {
        uint32_t h0 = pack_bhi(v.x, v.y), h1 = pack_bhi(v.z, v.w);
        uint32_t l0 = pack_blo(v.x, v.y, h0), l1 = pack_blo(v.z, v.w, h1);
        uint2 hh = {h0, h1}, ll = {l0, l1};
        ((uint2*)woh)[i] = hh;
        ((uint2*)wol)[i] = ll;
    }
}

// ====================== QKV projection (fp16, 1-2 MMA) ======================
// 128x128 tiles, BK=32, 3-stage ring. Tiles per stage: Ah | Al | W.
// z=0 (Q), z=1 (K): 1 MMA (A single).  z=2 (V): 2 MMAs (A hi+lo).
#define PTILE 10240            // 128 rows x 80 B
#define PSTG  30720            // 3 tiles
#define PSMEM (3 * PSTG)       // 92160

__device__ __forceinline__ void qkv_issue(
    uint32_t stg, const __half* ah, const __half* al, const __half* w,
    int row0, int col0, int k0, int tid, int has_lo) {
#pragma unroll
    for (int j = 0; j < 2; j++) {
        int idx = tid + j * 256;              // 0..511
        int r = idx >> 2, ch = idx & 3;
        uint32_t doff = (uint32_t)(r * 80 + ch * 16);
        size_t ga = (size_t)(row0 + r) * DIMC + k0 + ch * 8;
        size_t gw = (size_t)(col0 + r) * DIMC + k0 + ch * 8;
        cp16(stg + doff,             ah + ga);
        cp16(stg + 2 * PTILE + doff, w + gw);
        if (has_lo) cp16(stg + PTILE + doff, al + ga);
    }
}

__global__ __launch_bounds__(256, 2)
void proj_qkv_kernel(
    const __half* __restrict__ xq, const __half* __restrict__ xk,
    const __half* __restrict__ xvh, const __half* __restrict__ xvl,
    const __half* __restrict__ wq, const __half* __restrict__ wk,
    const __half* __restrict__ wv,
    const float* __restrict__ bq, const float* __restrict__ bk,
    const float* __restrict__ bv,
    __half* __restrict__ oq, __half* __restrict__ ok, __half* __restrict__ ov) {
    extern __shared__ __align__(16) char dsm[];
    const uint32_t sb = smem_u32(dsm);
    const int tid = threadIdx.x;
    const int wid = tid >> 5;
    const int lane = tid & 31;
    const int wm = wid >> 2;
    const int wn = wid & 3;
    const int row0 = blockIdx.x * 128;
    const int col0 = blockIdx.y * 128;
    const int z = blockIdx.z;
    const int has_lo = (z == 2);

    const __half* ah = z == 0 ? xq : z == 1 ? xk : xvh;
    const __half* al = xvl;
    const __half* w  = z == 0 ? wq : z == 1 ? wk : wv;
    const float* bias = z == 0 ? bq : z == 1 ? bk : bv;
    __half* op = z == 0 ? oq : z == 1 ? ok : ov;

    float bias_r[4][2];
#pragma unroll
    for (int j = 0; j < 4; j++) {
        int c = col0 + wn * 32 + j * 8 + (lane & 3) * 2;
        float2 bv2 = *(const float2*)&bias[c];
        bias_r[j][0] = bv2.x;
        bias_r[j][1] = bv2.y;
    }

    float acc[4][4][4];
#pragma unroll
    for (int i = 0; i < 4; i++)
#pragma unroll
        for (int j = 0; j < 4; j++)
#pragma unroll
            for (int k = 0; k < 4; k++) acc[i][j][k] = 0.f;

    const int lrow = (lane & 7) + (lane & 8);
    const int lcb = (lane >> 4) * 16;

    qkv_issue(sb, ah, al, w, row0, col0, 0, tid, has_lo);
    CP_COMMIT();
    qkv_issue(sb + PSTG, ah, al, w, row0, col0, 32, tid, has_lo);
    CP_COMMIT();

    for (int kt = 0; kt < 24; kt++) {
        if (kt < 23) { CP_WAIT1(); } else { CP_WAIT0(); }
        __syncthreads();
        if (kt < 22) {
            qkv_issue(sb + ((kt + 2) % 3) * PSTG, ah, al, w, row0, col0, (kt + 2) * 32, tid, has_lo);
            CP_COMMIT();
        }
        const uint32_t stg = sb + (kt % 3) * PSTG;
#pragma unroll
        for (int ks = 0; ks < 2; ks++) {
            const uint32_t kb = (uint32_t)(ks * 32 + lcb);
            uint32_t ahf[4][4], alf[4][4];
#pragma unroll
            for (int i = 0; i < 4; i++) {
                uint32_t off = (uint32_t)((wm * 64 + i * 16 + lrow) * 80) + kb;
                ldm4(ahf[i], stg + off);
                if (has_lo) ldm4(alf[i], stg + PTILE + off);
            }
#pragma unroll
            for (int g = 0; g < 2; g++) {
                uint32_t off = (uint32_t)((wn * 32 + g * 16 + lrow) * 80) + kb;
                uint32_t b4[4];
                ldm4(b4, stg + 2 * PTILE + off);
#pragma unroll
                for (int i = 0; i < 4; i++) {
                    mma_f16(acc[i][2 * g],     ahf[i], b4[0], b4[2]);
                    mma_f16(acc[i][2 * g + 1], ahf[i], b4[1], b4[3]);
                    if (has_lo) {
                        mma_f16(acc[i][2 * g],     alf[i], b4[0], b4[2]);
                        mma_f16(acc[i][2 * g + 1], alf[i], b4[1], b4[3]);
                    }
                }
            }
        }
    }

    // epilogue: write fp16 single into [b,h,t,d]
#pragma unroll
    for (int i = 0; i < 4; i++) {
        const int m0 = row0 + wm * 64 + i * 16 + (lane >> 2);
#pragma unroll
        for (int j = 0; j < 4; j++) {
            const int c = col0 + wn * 32 + j * 8 + (lane & 3) * 2;
            const int h = c >> 6, d = c & 63;
            float v0 = acc[i][j][0] + bias_r[j][0];
            float v1 = acc[i][j][1] + bias_r[j][1];
            float v2 = acc[i][j][2] + bias_r[j][0];
            float v3 = acc[i][j][3] + bias_r[j][1];
            {
                const int gr = m0, b = gr >> 11, t = gr & 2047;
                size_t oi = (((size_t)b * NH + h) * TLEN + t) * HD + d;
                *(uint32_t*)&op[oi] = packh(v0, v1);
            }
            {
                const int gr = m0 + 8, b = gr >> 11, t = gr & 2047;
                size_t oi = (((size_t)b * NH + h) * TLEN + t) * HD + d;
                *(uint32_t*)&op[oi] = packh(v2, v3);
            }
        }
    }
}

// ====================== O projection (bf16 split, 3 MMA) ====================
#define OTILE 10240
#define OSTG  40960            // Ah | Al | Wh | Wl
#define OSMEM (3 * OSTG)       // 122880

__device__ __forceinline__ void o_issue(
    uint32_t stg, const __nv_bfloat16* ah, const __nv_bfloat16* al,
    const __nv_bfloat16* wh, const __nv_bfloat16* wl,
    int row0, int col0, int k0, int tid) {
#pragma unroll
    for (int j = 0; j < 2; j++) {
        int idx = tid + j * 256;
        int r = idx >> 2, ch = idx & 3;
        uint32_t doff = (uint32_t)(r * 80 + ch * 16);
        size_t ga = (size_t)(row0 + r) * DIMC + k0 + ch * 8;
        size_t gw = (size_t)(col0 + r) * DIMC + k0 + ch * 8;
        cp16(stg + doff,             ah + ga);
        cp16(stg + OTILE + doff,     al + ga);
        cp16(stg + 2 * OTILE + doff, wh + gw);
        cp16(stg + 3 * OTILE + doff, wl + gw);
    }
}

__global__ __launch_bounds__(256, 1)
void proj_o_kernel(const __nv_bfloat16* __restrict__ ah, const __nv_bfloat16* __restrict__ al,
                   const __nv_bfloat16* __restrict__ wh, const __nv_bfloat16* __restrict__ wl,
                   const float* __restrict__ bias, float* __restrict__ out) {
    extern __shared__ __align__(16) char dsm[];
    const uint32_t sb = smem_u32(dsm);
    const int tid = threadIdx.x;
    const int wid = tid >> 5;
    const int lane = tid & 31;
    const int wm = wid >> 2;
    const int wn = wid & 3;
    const int row0 = blockIdx.x * 128;
    const int col0 = blockIdx.y * 128;

    float bias_r[4][2];
#pragma unroll
    for (int j = 0; j < 4; j++) {
        int c = col0 + wn * 32 + j * 8 + (lane & 3) * 2;
        float2 bv = *(const float2*)&bias[c];
        bias_r[j][0] = bv.x;
        bias_r[j][1] = bv.y;
    }

    float acc[4][4][4];
#pragma unroll
    for (int i = 0; i < 4; i++)
#pragma unroll
        for (int j = 0; j < 4; j++)
#pragma unroll
            for (int k = 0; k < 4; k++) acc[i][j][k] = 0.f;

    const int lrow = (lane & 7) + (lane & 8);
    const int lcb = (lane >> 4) * 16;

    o_issue(sb, ah, al, wh, wl, row0, col0, 0, tid);
    CP_COMMIT();
    o_issue(sb + OSTG, ah, al, wh, wl, row0, col0, 32, tid);
    CP_COMMIT();

    for (int kt = 0; kt < 24; kt++) {
        if (kt < 23) { CP_WAIT1(); } else { CP_WAIT0(); }
        __syncthreads();
        if (kt < 22) {
            o_issue(sb + ((kt + 2) % 3) * OSTG, ah, al, wh, wl, row0, col0, (kt + 2) * 32, tid);
            CP_COMMIT();
        }
        const uint32_t stg = sb + (kt % 3) * OSTG;
        const uint32_t sA_h = stg, sA_l = stg + OTILE, sW_h = stg + 2 * OTILE, sW_l = stg + 3 * OTILE;
#pragma unroll
        for (int ks = 0; ks < 2; ks++) {
            const uint32_t kb = (uint32_t)(ks * 32 + lcb);
            uint32_t ahf[4][4], alf[4][4];
#pragma unroll
            for (int i = 0; i < 4; i++) {
                uint32_t off = (uint32_t)((wm * 64 + i * 16 + lrow) * 80) + kb;
                ldm4(ahf[i], sA_h + off);
                ldm4(alf[i], sA_l + off);
            }
#pragma unroll
            for (int g = 0; g < 2; g++) {
                uint32_t off = (uint32_t)((wn * 32 + g * 16 + lrow) * 80) + kb;
                uint32_t bh4[4], bl4[4];
                ldm4(bh4, sW_h + off);
                ldm4(bl4, sW_l + off);
#pragma unroll
                for (int i = 0; i < 4; i++) {
                    mma_bf16(acc[i][2 * g],     ahf[i], bh4[0], bh4[2]);
                    mma_bf16(acc[i][2 * g],     ahf[i], bl4[0], bl4[2]);
                    mma_bf16(acc[i][2 * g],     alf[i], bh4[0], bh4[2]);
                    mma_bf16(acc[i][2 * g + 1], ahf[i], bh4[1], bh4[3]);
                    mma_bf16(acc[i][2 * g + 1], ahf[i], bl4[1], bl4[3]);
                    mma_bf16(acc[i][2 * g + 1], alf[i], bh4[1], bh4[3]);
                }
            }
        }
    }

#pragma unroll
    for (int i = 0; i < 4; i++) {
        const int m0 = row0 + wm * 64 + i * 16 + (lane >> 2);
#pragma unroll
        for (int j = 0; j < 4; j++) {
            const int c = col0 + wn * 32 + j * 8 + (lane & 3) * 2;
            float2 r01 = {acc[i][j][0] + bias_r[j][0], acc[i][j][1] + bias_r[j][1]};
            float2 r23 = {acc[i][j][2] + bias_r[j][0], acc[i][j][3] + bias_r[j][1]};
            *(float2*)&out[(size_t)m0 * DIMC + c] = r01;
            *(float2*)&out[(size_t)(m0 + 8) * DIMC + c] = r23;
        }
    }
}

// ====================== attention (fp16 single, 3-stage ring) ===============
// CTA: 64 queries, 128 threads. KV tiles 64 rows. stage = K | V = 16KB.
#define ATILE 8192
#define ASTG  16384
#define AT_SMEM (3 * ASTG)     // 49152

__device__ __forceinline__ void attn_issue_tile(
    uint32_t tilebase, const __half* src, int tid) {
#pragma unroll
    for (int j = 0; j < 4; j++) {
        int idx = tid + j * 128;     // 0..511
        int r = idx >> 3, ch = idx & 7;
        cp16(tilebase + SW128(r * 128 + ch * 16), src + (size_t)r * HD + ch * 8);
    }
}

__global__ __launch_bounds__(128, 4)
void attn_kernel(const __half* __restrict__ q, const __half* __restrict__ k,
                 const __half* __restrict__ v,
                 __nv_bfloat16* __restrict__ o_hi, __nv_bfloat16* __restrict__ o_lo) {
    extern __shared__ __align__(16) char dsm[];
    const uint32_t sb = smem_u32(dsm);
    const int tid = threadIdx.x;
    const int w = tid >> 5;
    const int lane = tid & 31;
    const int bh = blockIdx.y;
    const int q0 = blockIdx.x * 64;

    const __half* Q = q + ((size_t)bh * TLEN + q0) * HD;
    const __half* K = k + (size_t)bh * TLEN * HD;
    const __half* V = v + (size_t)bh * TLEN * HD;

    // stage Q through stage0, extract fragments
    attn_issue_tile(sb, Q, tid);
    CP_COMMIT();
    CP_WAIT0();
    __syncthreads();

    const int lrow = (lane & 7) + (lane & 8);
    const int lcb = (lane >> 4) * 16;
    uint32_t qa[4][4];
#pragma unroll
    for (int ks = 0; ks < 4; ks++) {
        uint32_t so = SW128((w * 16 + lrow) * 128 + ks * 32 + lcb);
        ldm4(qa[ks], sb + so);
    }
    __syncthreads();

    // issue KV tiles 0,1
    attn_issue_tile(sb, K, tid);
    attn_issue_tile(sb + ATILE, V, tid);
    CP_COMMIT();
    attn_issue_tile(sb + ASTG, K + (size_t)64 * HD, tid);
    attn_issue_tile(sb + ASTG + ATILE, V + (size_t)64 * HD, tid);
    CP_COMMIT();

    float oacc[8][4];
#pragma unroll
    for (int j = 0; j < 8; j++)
#pragma unroll
        for (int kk = 0; kk < 4; kk++) oacc[j][kk] = 0.f;
    float lsum0 = 0.f, lsum1 = 0.f;

    for (int t = 0; t < 32; t++) {
        if (t < 31) { CP_WAIT1(); } else { CP_WAIT0(); }
        __syncthreads();
        if (t < 30) {
            const uint32_t ib = sb + ((t + 2) % 3) * ASTG;
            attn_issue_tile(ib,         K + (size_t)(t + 2) * 64 * HD, tid);
            attn_issue_tile(ib + ATILE, V + (size_t)(t + 2) * 64 * HD, tid);
            CP_COMMIT();
        }
        const uint32_t cK = sb + (t % 3) * ASTG;
        const uint32_t cV = cK + ATILE;

        // S = Q K^T : 16 x 64 per warp
        float sc[8][4];
#pragma unroll
        for (int j = 0; j < 8; j++)
#pragma unroll
            for (int kk = 0; kk < 4; kk++) sc[j][kk] = 0.f;
#pragma unroll
        for (int ks = 0; ks < 4; ks++) {
            const uint32_t kb = (uint32_t)(ks * 32 + lcb);
#pragma unroll
            for (int g = 0; g < 4; g++) {
                uint32_t so = SW128((g * 16 + lrow) * 128 + kb);
                uint32_t b4[4];
                ldm4(b4, cK + so);
                mma_f16(sc[2 * g],     qa[ks], b4[0], b4[2]);
                mma_f16(sc[2 * g + 1], qa[ks], b4[1], b4[3]);
            }
        }

        // softmax (bounded scores) + pack P fp16
        uint32_t ph[8][2];
        float p0 = 0.f, p1 = 0.f;
#pragma unroll
        for (int j = 0; j < 8; j++) {
            float e0 = __expf(sc[j][0] * 0.125f);
            float e1 = __expf(sc[j][1] * 0.125f);
            float e2 = __expf(sc[j][2] * 0.125f);
            float e3 = __expf(sc[j][3] * 0.125f);
            p0 += e0 + e1;
            p1 += e2 + e3;
            ph[j][0] = packh(e0, e1);
            ph[j][1] = packh(e2, e3);
        }
        lsum0 += p0;
        lsum1 += p1;

        // O += P V
#pragma unroll
        for (int ks2 = 0; ks2 < 4; ks2++) {
            uint32_t pa[4] = {ph[2 * ks2][0], ph[2 * ks2][1], ph[2 * ks2 + 1][0], ph[2 * ks2 + 1][1]};
#pragma unroll
            for (int g = 0; g < 4; g++) {
                uint32_t so = SW128((ks2 * 16 + lrow) * 128 + g * 32 + lcb);
                uint32_t vf[4];
                ldm4t(vf, cV + so);
                mma_f16(oacc[2 * g],     pa, vf[0], vf[1]);
                mma_f16(oacc[2 * g + 1], pa, vf[2], vf[3]);
            }
        }
    }

    lsum0 += __shfl_xor_sync(0xffffffffu, lsum0, 1);
    lsum0 += __shfl_xor_sync(0xffffffffu, lsum0, 2);
    lsum1 += __shfl_xor_sync(0xffffffffu, lsum1, 1);
    lsum1 += __shfl_xor_sync(0xffffffffu, lsum1, 2);
    const float inv0 = 1.f / lsum0;
    const float inv1 = 1.f / lsum1;

    const int b = bh / NH, h = bh % NH;
    const int qr0 = q0 + w * 16 + (lane >> 2);
    const int qr1 = qr0 + 8;
    size_t base0 = ((size_t)b * TLEN + qr0) * DIMC + h * HD + (lane & 3) * 2;
    size_t base1 = ((size_t)b * TLEN + qr1) * DIMC + h * HD + (lane & 3) * 2;
#pragma unroll
    for (int g = 0; g < 8; g++) {
        float x0 = oacc[g][0] * inv0, y0 = oacc[g][1] * inv0;
        float x1 = oacc[g][2] * inv1, y1 = oacc[g][3] * inv1;
        uint32_t h0 = pack_bhi(x0, y0), h1 = pack_bhi(x1, y1);
        *(uint32_t*)&o_hi[base0 + g * 8] = h0;
        *(uint32_t*)&o_lo[base0 + g * 8] = pack_blo(x0, y0, h0);
        *(uint32_t*)&o_hi[base1 + g * 8] = h1;
        *(uint32_t*)&o_lo[base1 + g * 8] = pack_blo(x1, y1, h1);
    }
}

// ====================== launch ==============================================
extern "C" void kernel_launch(void* const* d_in, const int* in_sizes, int n_in,
                              void* d_out, int out_size) {
    const float* q_in = (const float*)d_in[0];
    const float* k_in = (const float*)d_in[1];
    const float* v_in = (const float*)d_in[2];
    const float* Wq = (const float*)d_in[3];
    const float* bq = (const float*)d_in[4];
    const float* Wk = (const float*)d_in[5];
    const float* bk = (const float*)d_in[6];
    const float* Wv = (const float*)d_in[7];
    const float* bv = (const float*)d_in[8];
    const float* Wo = (const float*)d_in[9];
    const float* bo = (const float*)d_in[10];
    float* out = (float*)d_out;

    __half *xq, *xk, *xvh, *xvl, *wq, *wk, *wv, *pq, *pk, *pv;
    __nv_bfloat16 *woh, *wol, *pah, *pal;
    cudaGetSymbolAddress((void**)&xq, g_xq);
    cudaGetSymbolAddress((void**)&xk, g_xk);
    cudaGetSymbolAddress((void**)&xvh, g_xv_h);
    cudaGetSymbolAddress((void**)&xvl, g_xv_l);
    cudaGetSymbolAddress((void**)&wq, g_wq);
    cudaGetSymbolAddress((void**)&wk, g_wk);
    cudaGetSymbolAddress((void**)&wv, g_wv);
    cudaGetSymbolAddress((void**)&woh, g_wo_hi);
    cudaGetSymbolAddress((void**)&wol, g_wo_lo);
    cudaGetSymbolAddress((void**)&pq, g_q);
    cudaGetSymbolAddress((void**)&pk, g_k);
    cudaGetSymbolAddress((void**)&pv, g_v);
    cudaGetSymbolAddress((void**)&pah, g_a_hi);
    cudaGetSymbolAddress((void**)&pal, g_a_lo);

    cudaFuncSetAttribute(proj_qkv_kernel, cudaFuncAttributeMaxDynamicSharedMemorySize, PSMEM);
    cudaFuncSetAttribute(proj_o_kernel, cudaFuncAttributeMaxDynamicSharedMemorySize, OSMEM);
    cudaFuncSetAttribute(attn_kernel, cudaFuncAttributeMaxDynamicSharedMemorySize, AT_SMEM);

    dim3 sxg(MROWS * DIMC / 4 / 256, 3);
    split_x_kernel<<<sxg, 256>>>(q_in, k_in, v_in, xq, xk, xvh, xvl);
    dim3 swg(DIMC * DIMC / 4 / 256, 4);
    split_w_kernel<<<swg, 256>>>(Wq, Wk, Wv, Wo, wq, wk, wv, woh, wol);

    dim3 pgrid(MROWS / 128, DIMC / 128, 3);   // 32 x 6 x 3
    proj_qkv_kernel<<<pgrid, 256, PSMEM>>>(xq, xk, xvh, xvl, wq, wk, wv,
                                           bq, bk, bv, pq, pk, pv);

    dim3 agrid(TLEN / 64, BSZ * NH);           // 32 x 24
    attn_kernel<<<agrid, 128, AT_SMEM>>>(pq, pk, pv, pah, pal);

    dim3 ogrid(MROWS / 128, DIMC / 128);
    proj_o_kernel<<<ogrid, 256, OSMEM>>>(pah, pal, woh, wol, bo, out);
}

// round 8
// speedup vs baseline: 1.9610x; 1.7566x over previous
#include <cuda_runtime.h>
#include <cuda_bf16.h>
#include <cuda_fp16.h>
#include <stdint.h>

#define DIMC 768
#define NH 12
#define HD 64
#define BSZ 2
#define TLEN 2048
#define MROWS 4096

// score_scale(0.125) * log2(e)
#define QSCALE 0.180336879f

// ---------------- scratch ----------------
__device__ __half g_xq[MROWS * DIMC];                          // fp16 inputs
__device__ __half g_xk[MROWS * DIMC];
__device__ __half g_xv_h[MROWS * DIMC], g_xv_l[MROWS * DIMC];  // V input split fp16
__device__ __half g_wq[DIMC * DIMC], g_wk[DIMC * DIMC], g_wv[DIMC * DIMC];
__device__ __half g_wo_h[DIMC * DIMC], g_wo_l[DIMC * DIMC];    // Wo fp16 split
__device__ __half g_q[MROWS * DIMC], g_k[MROWS * DIMC], g_v[MROWS * DIMC];  // [b,h,t,d]
__device__ __half g_a[MROWS * DIMC];                           // attn out [b,t,c] fp16

// ---------------- helpers ----------------
__device__ __forceinline__ uint32_t smem_u32(const void* p) {
    uint32_t a;
    asm("{ .reg .u64 t; cvta.to.shared.u64 t, %1; cvt.u32.u64 %0, t; }" : "=r"(a) : "l"(p));
    return a;
}
__device__ __forceinline__ void cp16(uint32_t dst, const void* src) {
    asm volatile("cp.async.cg.shared.global [%0], [%1], 16;" :: "r"(dst), "l"(src) : "memory");
}
#define CP_COMMIT() asm volatile("cp.async.commit_group;" ::: "memory")
#define CP_WAIT0()  asm volatile("cp.async.wait_group 0;" ::: "memory")
#define CP_WAIT1()  asm volatile("cp.async.wait_group 1;" ::: "memory")
__device__ __forceinline__ void ldm4(uint32_t* r, uint32_t addr) {
    asm volatile("ldmatrix.sync.aligned.m8n8.x4.shared.b16 {%0,%1,%2,%3}, [%4];"
        : "=r"(r[0]), "=r"(r[1]), "=r"(r[2]), "=r"(r[3]) : "r"(addr));
}
__device__ __forceinline__ void ldm4t(uint32_t* r, uint32_t addr) {
    asm volatile("ldmatrix.sync.aligned.m8n8.x4.trans.shared.b16 {%0,%1,%2,%3}, [%4];"
        : "=r"(r[0]), "=r"(r[1]), "=r"(r[2]), "=r"(r[3]) : "r"(addr));
}
__device__ __forceinline__ void mma_f16(float* c, const uint32_t* a, uint32_t b0, uint32_t b1) {
    asm volatile("mma.sync.aligned.m16n8k16.row.col.f32.f16.f16.f32 "
        "{%0,%1,%2,%3}, {%4,%5,%6,%7}, {%8,%9}, {%0,%1,%2,%3};"
        : "+f"(c[0]), "+f"(c[1]), "+f"(c[2]), "+f"(c[3])
        : "r"(a[0]), "r"(a[1]), "r"(a[2]), "r"(a[3]), "r"(b0), "r"(b1));
}
__device__ __forceinline__ uint32_t packh(float x, float y) {
    __half2 h = __floats2half2_rn(x, y);
    return *(uint32_t*)&h;
}
__device__ __forceinline__ float ex2f(float x) {
    float r;
    asm("ex2.approx.f32 %0, %1;" : "=f"(r) : "f"(x));
    return r;
}

#define SW128(o) ((uint32_t)(o) ^ ((((uint32_t)(o)) >> 3) & 0x70))

// ====================== split kernels =======================================
__global__ __launch_bounds__(256)
void split_x_kernel(const float* __restrict__ s0, const float* __restrict__ s1,
                    const float* __restrict__ s2,
                    __half* xq, __half* xk, __half* xvh, __half* xvl) {
    int z = blockIdx.y;
    int i = blockIdx.x * 256 + threadIdx.x;
    const float* s = z == 0 ? s0 : z == 1 ? s1 : s2;
    float4 v = ((const float4*)s)[i];
    if (z < 2) {
        __half* d = z == 0 ? xq : xk;
        uint2 o = {packh(v.x, v.y), packh(v.z, v.w)};
        ((uint2*)d)[i] = o;
    } else {
        uint32_t h0 = packh(v.x, v.y), h1 = packh(v.z, v.w);
        __half2 a = *(__half2*)&h0, b = *(__half2*)&h1;
        uint32_t l0 = packh(v.x - __half2float(a.x), v.y - __half2float(a.y));
        uint32_t l1 = packh(v.z - __half2float(b.x), v.w - __half2float(b.y));
        uint2 hh = {h0, h1}, ll = {l0, l1};
        ((uint2*)xvh)[i] = hh;
        ((uint2*)xvl)[i] = ll;
    }
}

__global__ __launch_bounds__(256)
void split_w_kernel(const float* __restrict__ s0, const float* __restrict__ s1,
                    const float* __restrict__ s2, const float* __restrict__ s3,
                    __half* wq, __half* wk, __half* wv,
                    __half* woh, __half* wol) {
    int z = blockIdx.y;
    int i = blockIdx.x * 256 + threadIdx.x;
    const float* s = z == 0 ? s0 : z == 1 ? s1 : z == 2 ? s2 : s3;
    float4 v = ((const float4*)s)[i];
    if (z < 3) {
        __half* d = z == 0 ? wq : z == 1 ? wk : wv;
        uint2 o = {packh(v.x, v.y), packh(v.z, v.w)};
        ((uint2*)d)[i] = o;
    } else {
        uint32_t h0 = packh(v.x, v.y), h1 = packh(v.z, v.w);
        __half2 a = *(__half2*)&h0, b = *(__half2*)&h1;
        uint32_t l0 = packh(v.x - __half2float(a.x), v.y - __half2float(a.y));
        uint32_t l1 = packh(v.z - __half2float(b.x), v.w - __half2float(b.y));
        uint2 hh = {h0, h1}, ll = {l0, l1};
        ((uint2*)woh)[i] = hh;
        ((uint2*)wol)[i] = ll;
    }
}

// ====================== QKV projection (64x64 warp tiles) ===================
// 128x128 CTA tile, 4 warps (2x2), warp tile 64x64. BK=32, 3-stage ring.
// z=0 (Q, scaled), z=1 (K): 1 MMA. z=2 (V): 2 MMAs (A hi+lo).
#define PTILE 10240            // 128 rows x 80 B
#define PSTG  30720            // A | Alo | W
#define PSMEM (3 * PSTG)       // 92160

__device__ __forceinline__ void qkv_issue(
    uint32_t stg, const __half* a, const __half* alo, const __half* w,
    int row0, int col0, int k0, int tid, int has_lo) {
#pragma unroll
    for (int j = 0; j < 4; j++) {
        int idx = tid + j * 128;              // 0..511
        int r = idx >> 2, ch = idx & 3;
        uint32_t doff = (uint32_t)(r * 80 + ch * 16);
        size_t ga = (size_t)(row0 + r) * DIMC + k0 + ch * 8;
        size_t gw = (size_t)(col0 + r) * DIMC + k0 + ch * 8;
        cp16(stg + doff,             a + ga);
        cp16(stg + 2 * PTILE + doff, w + gw);
        if (has_lo) cp16(stg + PTILE + doff, alo + ga);
    }
}

__global__ __launch_bounds__(128, 2)
void proj_qkv_kernel(
    const __half* __restrict__ xq, const __half* __restrict__ xk,
    const __half* __restrict__ xvh, const __half* __restrict__ xvl,
    const __half* __restrict__ wq, const __half* __restrict__ wk,
    const __half* __restrict__ wv,
    const float* __restrict__ bq, const float* __restrict__ bk,
    const float* __restrict__ bv,
    __half* __restrict__ oq, __half* __restrict__ ok, __half* __restrict__ ov) {
    extern __shared__ __align__(16) char dsm[];
    const uint32_t sb = smem_u32(dsm);
    const int tid = threadIdx.x;
    const int wid = tid >> 5;
    const int lane = tid & 31;
    const int wm = wid >> 1;       // 0..1
    const int wn = wid & 1;        // 0..1
    const int row0 = blockIdx.x * 128;
    const int col0 = blockIdx.y * 128;
    const int z = blockIdx.z;
    const int has_lo = (z == 2);
    const float oscale = (z == 0) ? QSCALE : 1.f;

    const __half* a  = z == 0 ? xq : z == 1 ? xk : xvh;
    const __half* w  = z == 0 ? wq : z == 1 ? wk : wv;
    const float* bias = z == 0 ? bq : z == 1 ? bk : bv;
    __half* op = z == 0 ? oq : z == 1 ? ok : ov;

    float bias_r[8][2];
#pragma unroll
    for (int j = 0; j < 8; j++) {
        int c = col0 + wn * 64 + j * 8 + (lane & 3) * 2;
        float2 bv2 = *(const float2*)&bias[c];
        bias_r[j][0] = bv2.x;
        bias_r[j][1] = bv2.y;
    }

    float acc[4][8][4];
#pragma unroll
    for (int i = 0; i < 4; i++)
#pragma unroll
        for (int j = 0; j < 8; j++)
#pragma unroll
            for (int k = 0; k < 4; k++) acc[i][j][k] = 0.f;

    const int lrow = (lane & 7) + (lane & 8);
    const int lcb = (lane >> 4) * 16;

    qkv_issue(sb, a, xvl, w, row0, col0, 0, tid, has_lo);
    CP_COMMIT();
    qkv_issue(sb + PSTG, a, xvl, w, row0, col0, 32, tid, has_lo);
    CP_COMMIT();

    for (int kt = 0; kt < 24; kt++) {
        if (kt < 23) { CP_WAIT1(); } else { CP_WAIT0(); }
        __syncthreads();
        if (kt < 22) {
            qkv_issue(sb + ((kt + 2) % 3) * PSTG, a, xvl, w, row0, col0, (kt + 2) * 32, tid, has_lo);
            CP_COMMIT();
        }
        const uint32_t stg = sb + (kt % 3) * PSTG;
#pragma unroll
        for (int ks = 0; ks < 2; ks++) {
            const uint32_t kb = (uint32_t)(ks * 32 + lcb);
            uint32_t af[4][4], alf[4][4];
#pragma unroll
            for (int i = 0; i < 4; i++) {
                uint32_t off = (uint32_t)((wm * 64 + i * 16 + lrow) * 80) + kb;
                ldm4(af[i], stg + off);
                if (has_lo) ldm4(alf[i], stg + PTILE + off);
            }
#pragma unroll
            for (int g = 0; g < 4; g++) {
                uint32_t off = (uint32_t)((wn * 64 + g * 16 + lrow) * 80) + kb;
                uint32_t b4[4];
                ldm4(b4, stg + 2 * PTILE + off);
#pragma unroll
                for (int i = 0; i < 4; i++) {
                    mma_f16(acc[i][2 * g],     af[i], b4[0], b4[2]);
                    mma_f16(acc[i][2 * g + 1], af[i], b4[1], b4[3]);
                    if (has_lo) {
                        mma_f16(acc[i][2 * g],     alf[i], b4[0], b4[2]);
                        mma_f16(acc[i][2 * g + 1], alf[i], b4[1], b4[3]);
                    }
                }
            }
        }
    }

    // epilogue: write fp16 into [b,h,t,d], Q scaled by QSCALE
#pragma unroll
    for (int i = 0; i < 4; i++) {
        const int m0 = row0 + wm * 64 + i * 16 + (lane >> 2);
#pragma unroll
        for (int j = 0; j < 8; j++) {
            const int c = col0 + wn * 64 + j * 8 + (lane & 3) * 2;
            const int h = c >> 6, d = c & 63;
            float v0 = (acc[i][j][0] + bias_r[j][0]) * oscale;
            float v1 = (acc[i][j][1] + bias_r[j][1]) * oscale;
            float v2 = (acc[i][j][2] + bias_r[j][0]) * oscale;
            float v3 = (acc[i][j][3] + bias_r[j][1]) * oscale;
            {
                const int gr = m0, b = gr >> 11, t = gr & 2047;
                size_t oi = (((size_t)b * NH + h) * TLEN + t) * HD + d;
                *(uint32_t*)&op[oi] = packh(v0, v1);
            }
            {
                const int gr = m0 + 8, b = gr >> 11, t = gr & 2047;
                size_t oi = (((size_t)b * NH + h) * TLEN + t) * HD + d;
                *(uint32_t*)&op[oi] = packh(v2, v3);
            }
        }
    }
}

// ====================== O projection (fp16, 2 MMA, occ 2) ===================
#define OTILE 10240
#define OSTG  30720            // A | Wh | Wl
#define OSMEM (3 * OSTG)       // 92160

__device__ __forceinline__ void o_issue(
    uint32_t stg, const __half* a, const __half* wh, const __half* wl,
    int row0, int col0, int k0, int tid) {
#pragma unroll
    for (int j = 0; j < 2; j++) {
        int idx = tid + j * 256;
        int r = idx >> 2, ch = idx & 3;
        uint32_t doff = (uint32_t)(r * 80 + ch * 16);
        size_t ga = (size_t)(row0 + r) * DIMC + k0 + ch * 8;
        size_t gw = (size_t)(col0 + r) * DIMC + k0 + ch * 8;
        cp16(stg + doff,             a + ga);
        cp16(stg + OTILE + doff,     wh + gw);
        cp16(stg + 2 * OTILE + doff, wl + gw);
    }
}

__global__ __launch_bounds__(256, 2)
void proj_o_kernel(const __half* __restrict__ a,
                   const __half* __restrict__ wh, const __half* __restrict__ wl,
                   const float* __restrict__ bias, float* __restrict__ out) {
    extern __shared__ __align__(16) char dsm[];
    const uint32_t sb = smem_u32(dsm);
    const int tid = threadIdx.x;
    const int wid = tid >> 5;
    const int lane = tid & 31;
    const int wm = wid >> 2;       // 0..1
    const int wn = wid & 3;        // 0..3
    const int row0 = blockIdx.x * 128;
    const int col0 = blockIdx.y * 128;

    float bias_r[4][2];
#pragma unroll
    for (int j = 0; j < 4; j++) {
        int c = col0 + wn * 32 + j * 8 + (lane & 3) * 2;
        float2 bv = *(const float2*)&bias[c];
        bias_r[j][0] = bv.x;
        bias_r[j][1] = bv.y;
    }

    float acc[4][4][4];
#pragma unroll
    for (int i = 0; i < 4; i++)
#pragma unroll
        for (int j = 0; j < 4; j++)
#pragma unroll
            for (int k = 0; k < 4; k++) acc[i][j][k] = 0.f;

    const int lrow = (lane & 7) + (lane & 8);
    const int lcb = (lane >> 4) * 16;

    o_issue(sb, a, wh, wl, row0, col0, 0, tid);
    CP_COMMIT();
    o_issue(sb + OSTG, a, wh, wl, row0, col0, 32, tid);
    CP_COMMIT();

    for (int kt = 0; kt < 24; kt++) {
        if (kt < 23) { CP_WAIT1(); } else { CP_WAIT0(); }
        __syncthreads();
        if (kt < 22) {
            o_issue(sb + ((kt + 2) % 3) * OSTG, a, wh, wl, row0, col0, (kt + 2) * 32, tid);
            CP_COMMIT();
        }
        const uint32_t stg = sb + (kt % 3) * OSTG;
#pragma unroll
        for (int ks = 0; ks < 2; ks++) {
            const uint32_t kb = (uint32_t)(ks * 32 + lcb);
            uint32_t af[4][4];
#pragma unroll
            for (int i = 0; i < 4; i++) {
                uint32_t off = (uint32_t)((wm * 64 + i * 16 + lrow) * 80) + kb;
                ldm4(af[i], stg + off);
            }
#pragma unroll
            for (int g = 0; g < 2; g++) {
                uint32_t off = (uint32_t)((wn * 32 + g * 16 + lrow) * 80) + kb;
                uint32_t bh4[4], bl4[4];
                ldm4(bh4, stg + OTILE + off);
                ldm4(bl4, stg + 2 * OTILE + off);
#pragma unroll
                for (int i = 0; i < 4; i++) {
                    mma_f16(acc[i][2 * g],     af[i], bh4[0], bh4[2]);
                    mma_f16(acc[i][2 * g],     af[i], bl4[0], bl4[2]);
                    mma_f16(acc[i][2 * g + 1], af[i], bh4[1], bh4[3]);
                    mma_f16(acc[i][2 * g + 1], af[i], bl4[1], bl4[3]);
                }
            }
        }
    }

#pragma unroll
    for (int i = 0; i < 4; i++) {
        const int m0 = row0 + wm * 64 + i * 16 + (lane >> 2);
#pragma unroll
        for (int j = 0; j < 4; j++) {
            const int c = col0 + wn * 32 + j * 8 + (lane & 3) * 2;
            float2 r01 = {acc[i][j][0] + bias_r[j][0], acc[i][j][1] + bias_r[j][1]};
            float2 r23 = {acc[i][j][2] + bias_r[j][0], acc[i][j][3] + bias_r[j][1]};
            *(float2*)&out[(size_t)m0 * DIMC + c] = r01;
            *(float2*)&out[(size_t)(m0 + 8) * DIMC + c] = r23;
        }
    }
}

// ====================== attention (fp16, ex2, 3-stage ring) =================
#define ATILE 8192
#define ASTG  16384
#define AT_SMEM (3 * ASTG)     // 49152

__device__ __forceinline__ void attn_issue_tile(
    uint32_t tilebase, const __half* src, int tid) {
#pragma unroll
    for (int j = 0; j < 4; j++) {
        int idx = tid + j * 128;
        int r = idx >> 3, ch = idx & 7;
        cp16(tilebase + SW128(r * 128 + ch * 16), src + (size_t)r * HD + ch * 8);
    }
}

__global__ __launch_bounds__(128, 4)
void attn_kernel(const __half* __restrict__ q, const __half* __restrict__ k,
                 const __half* __restrict__ v, __half* __restrict__ o) {
    extern __shared__ __align__(16) char dsm[];
    const uint32_t sb = smem_u32(dsm);
    const int tid = threadIdx.x;
    const int w = tid >> 5;
    const int lane = tid & 31;
    const int bh = blockIdx.y;
    const int q0 = blockIdx.x * 64;

    const __half* Q = q + ((size_t)bh * TLEN + q0) * HD;
    const __half* K = k + (size_t)bh * TLEN * HD;
    const __half* V = v + (size_t)bh * TLEN * HD;

    attn_issue_tile(sb, Q, tid);
    CP_COMMIT();
    CP_WAIT0();
    __syncthreads();

    const int lrow = (lane & 7) + (lane & 8);
    const int lcb = (lane >> 4) * 16;
    uint32_t qa[4][4];
#pragma unroll
    for (int ks = 0; ks < 4; ks++) {
        uint32_t so = SW128((w * 16 + lrow) * 128 + ks * 32 + lcb);
        ldm4(qa[ks], sb + so);
    }
    __syncthreads();

    attn_issue_tile(sb, K, tid);
    attn_issue_tile(sb + ATILE, V, tid);
    CP_COMMIT();
    attn_issue_tile(sb + ASTG, K + (size_t)64 * HD, tid);
    attn_issue_tile(sb + ASTG + ATILE, V + (size_t)64 * HD, tid);
    CP_COMMIT();

    float oacc[8][4];
#pragma unroll
    for (int j = 0; j < 8; j++)
#pragma unroll
        for (int kk = 0; kk < 4; kk++) oacc[j][kk] = 0.f;
    float lsum0 = 0.f, lsum1 = 0.f;

    for (int t = 0; t < 32; t++) {
        if (t < 31) { CP_WAIT1(); } else { CP_WAIT0(); }
        __syncthreads();
        if (t < 30) {
            const uint32_t ib = sb + ((t + 2) % 3) * ASTG;
            attn_issue_tile(ib,         K + (size_t)(t + 2) * 64 * HD, tid);
            attn_issue_tile(ib + ATILE, V + (size_t)(t + 2) * 64 * HD, tid);
            CP_COMMIT();
        }
        const uint32_t cK = sb + (t % 3) * ASTG;
        const uint32_t cV = cK + ATILE;

        float sc[8][4];
#pragma unroll
        for (int j = 0; j < 8; j++)
#pragma unroll
            for (int kk = 0; kk < 4; kk++) sc[j][kk] = 0.f;
#pragma unroll
        for (int ks = 0; ks < 4; ks++) {
            const uint32_t kb = (uint32_t)(ks * 32 + lcb);
#pragma unroll
            for (int g = 0; g < 4; g++) {
                uint32_t so = SW128((g * 16 + lrow) * 128 + kb);
                uint32_t b4[4];
                ldm4(b4, cK + so);
                mma_f16(sc[2 * g],     qa[ks], b4[0], b4[2]);
                mma_f16(sc[2 * g + 1], qa[ks], b4[1], b4[3]);
            }
        }

        // p = exp2(s~) (scale folded into Q); pack fp16
        uint32_t ph[8][2];
        float p0 = 0.f, p1 = 0.f;
#pragma unroll
        for (int j = 0; j < 8; j++) {
            float e0 = ex2f(sc[j][0]);
            float e1 = ex2f(sc[j][1]);
            float e2 = ex2f(sc[j][2]);
            float e3 = ex2f(sc[j][3]);
            p0 += e0 + e1;
            p1 += e2 + e3;
            ph[j][0] = packh(e0, e1);
            ph[j][1] = packh(e2, e3);
        }
        lsum0 += p0;
        lsum1 += p1;

#pragma unroll
        for (int ks2 = 0; ks2 < 4; ks2++) {
            uint32_t pa[4] = {ph[2 * ks2][0], ph[2 * ks2][1], ph[2 * ks2 + 1][0], ph[2 * ks2 + 1][1]};
#pragma unroll
            for (int g = 0; g < 4; g++) {
                uint32_t so = SW128((ks2 * 16 + lrow) * 128 + g * 32 + lcb);
                uint32_t vf[4];
                ldm4t(vf, cV + so);
                mma_f16(oacc[2 * g],     pa, vf[0], vf[1]);
                mma_f16(oacc[2 * g + 1], pa, vf[2], vf[3]);
            }
        }
    }

    lsum0 += __shfl_xor_sync(0xffffffffu, lsum0, 1);
    lsum0 += __shfl_xor_sync(0xffffffffu, lsum0, 2);
    lsum1 += __shfl_xor_sync(0xffffffffu, lsum1, 1);
    lsum1 += __shfl_xor_sync(0xffffffffu, lsum1, 2);
    const float inv0 = 1.f / lsum0;
    const float inv1 = 1.f / lsum1;

    const int b = bh / NH, h = bh % NH;
    const int qr0 = q0 + w * 16 + (lane >> 2);
    const int qr1 = qr0 + 8;
    size_t base0 = ((size_t)b * TLEN + qr0) * DIMC + h * HD + (lane & 3) * 2;
    size_t base1 = ((size_t)b * TLEN + qr1) * DIMC + h * HD + (lane & 3) * 2;
#pragma unroll
    for (int g = 0; g < 8; g++) {
        *(uint32_t*)&o[base0 + g * 8] = packh(oacc[g][0] * inv0, oacc[g][1] * inv0);
        *(uint32_t*)&o[base1 + g * 8] = packh(oacc[g][2] * inv1, oacc[g][3] * inv1);
    }
}

// ====================== launch ==============================================
extern "C" void kernel_launch(void* const* d_in, const int* in_sizes, int n_in,
                              void* d_out, int out_size) {
    const float* q_in = (const float*)d_in[0];
    const float* k_in = (const float*)d_in[1];
    const float* v_in = (const float*)d_in[2];
    const float* Wq = (const float*)d_in[3];
    const float* bq = (const float*)d_in[4];
    const float* Wk = (const float*)d_in[5];
    const float* bk = (const float*)d_in[6];
    const float* Wv = (const float*)d_in[7];
    const float* bv = (const float*)d_in[8];
    const float* Wo = (const float*)d_in[9];
    const float* bo = (const float*)d_in[10];
    float* out = (float*)d_out;

    __half *xq, *xk, *xvh, *xvl, *wq, *wk, *wv, *woh, *wol, *pq, *pk, *pv, *pa;
    cudaGetSymbolAddress((void**)&xq, g_xq);
    cudaGetSymbolAddress((void**)&xk, g_xk);
    cudaGetSymbolAddress((void**)&xvh, g_xv_h);
    cudaGetSymbolAddress((void**)&xvl, g_xv_l);
    cudaGetSymbolAddress((void**)&wq, g_wq);
    cudaGetSymbolAddress((void**)&wk, g_wk);
    cudaGetSymbolAddress((void**)&wv, g_wv);
    cudaGetSymbolAddress((void**)&woh, g_wo_h);
    cudaGetSymbolAddress((void**)&wol, g_wo_l);
    cudaGetSymbolAddress((void**)&pq, g_q);
    cudaGetSymbolAddress((void**)&pk, g_k);
    cudaGetSymbolAddress((void**)&pv, g_v);
    cudaGetSymbolAddress((void**)&pa, g_a);

    cudaFuncSetAttribute(proj_qkv_kernel, cudaFuncAttributeMaxDynamicSharedMemorySize, PSMEM);
    cudaFuncSetAttribute(proj_o_kernel, cudaFuncAttributeMaxDynamicSharedMemorySize, OSMEM);
    cudaFuncSetAttribute(attn_kernel, cudaFuncAttributeMaxDynamicSharedMemorySize, AT_SMEM);

    dim3 sxg(MROWS * DIMC / 4 / 256, 3);
    split_x_kernel<<<sxg, 256>>>(q_in, k_in, v_in, xq, xk, xvh, xvl);
    dim3 swg(DIMC * DIMC / 4 / 256, 4);
    split_w_kernel<<<swg, 256>>>(Wq, Wk, Wv, Wo, wq, wk, wv, woh, wol);

    dim3 pgrid(MROWS / 128, DIMC / 128, 3);   // 32 x 6 x 3
    proj_qkv_kernel<<<pgrid, 128, PSMEM>>>(xq, xk, xvh, xvl, wq, wk, wv,
                                           bq, bk, bv, pq, pk, pv);

    dim3 agrid(TLEN / 64, BSZ * NH);           // 32 x 24
    attn_kernel<<<agrid, 128, AT_SMEM>>>(pq, pk, pv, pa);

    dim3 ogrid(MROWS / 128, DIMC / 128);
    proj_o_kernel<<<ogrid, 256, OSMEM>>>(pa, woh, wol, bo, out);
}

// round 9
// speedup vs baseline: 2.0357x; 1.0381x over previous
#include <cuda_runtime.h>
#include <cuda_bf16.h>
#include <cuda_fp16.h>
#include <stdint.h>

#define DIMC 768
#define NH 12
#define HD 64
#define BSZ 2
#define TLEN 2048
#define MROWS 4096

// score_scale(0.125) * log2(e)
#define QSCALE 0.180336879f

// ---------------- scratch ----------------
__device__ __half g_xq[MROWS * DIMC];                          // fp16 inputs
__device__ __half g_xk[MROWS * DIMC];
__device__ __half g_xv_h[MROWS * DIMC], g_xv_l[MROWS * DIMC];  // V input split fp16
__device__ __half g_wq[DIMC * DIMC], g_wk[DIMC * DIMC], g_wv[DIMC * DIMC];
__device__ __half g_wo_h[DIMC * DIMC], g_wo_l[DIMC * DIMC];    // Wo fp16 split
__device__ __half g_q[MROWS * DIMC], g_k[MROWS * DIMC], g_v[MROWS * DIMC];  // [b,h,t,d]
__device__ __half g_a[MROWS * DIMC];                           // attn out [b,t,c] fp16

// ---------------- helpers ----------------
__device__ __forceinline__ uint32_t smem_u32(const void* p) {
    uint32_t a;
    asm("{ .reg .u64 t; cvta.to.shared.u64 t, %1; cvt.u32.u64 %0, t; }" : "=r"(a) : "l"(p));
    return a;
}
__device__ __forceinline__ void cp16(uint32_t dst, const void* src) {
    asm volatile("cp.async.cg.shared.global [%0], [%1], 16;" :: "r"(dst), "l"(src) : "memory");
}
#define CP_COMMIT() asm volatile("cp.async.commit_group;" ::: "memory")
#define CP_WAIT0()  asm volatile("cp.async.wait_group 0;" ::: "memory")
#define CP_WAIT1()  asm volatile("cp.async.wait_group 1;" ::: "memory")
#define CP_WAIT2()  asm volatile("cp.async.wait_group 2;" ::: "memory")
__device__ __forceinline__ void ldm4(uint32_t* r, uint32_t addr) {
    asm volatile("ldmatrix.sync.aligned.m8n8.x4.shared.b16 {%0,%1,%2,%3}, [%4];"
        : "=r"(r[0]), "=r"(r[1]), "=r"(r[2]), "=r"(r[3]) : "r"(addr));
}
__device__ __forceinline__ void ldm4t(uint32_t* r, uint32_t addr) {
    asm volatile("ldmatrix.sync.aligned.m8n8.x4.trans.shared.b16 {%0,%1,%2,%3}, [%4];"
        : "=r"(r[0]), "=r"(r[1]), "=r"(r[2]), "=r"(r[3]) : "r"(addr));
}
__device__ __forceinline__ void mma_f16(float* c, const uint32_t* a, uint32_t b0, uint32_t b1) {
    asm volatile("mma.sync.aligned.m16n8k16.row.col.f32.f16.f16.f32 "
        "{%0,%1,%2,%3}, {%4,%5,%6,%7}, {%8,%9}, {%0,%1,%2,%3};"
        : "+f"(c[0]), "+f"(c[1]), "+f"(c[2]), "+f"(c[3])
        : "r"(a[0]), "r"(a[1]), "r"(a[2]), "r"(a[3]), "r"(b0), "r"(b1));
}
__device__ __forceinline__ uint32_t packh(float x, float y) {
    __half2 h = __floats2half2_rn(x, y);
    return *(uint32_t*)&h;
}
__device__ __forceinline__ float ex2f(float x) {
    float r;
    asm("ex2.approx.f32 %0, %1;" : "=f"(r) : "f"(x));
    return r;
}

#define SW128(o) ((uint32_t)(o) ^ ((((uint32_t)(o)) >> 3) & 0x70))

// ====================== merged split kernel =================================
// blocks [0, 9216): inputs (3 tensors x 3072 blocks)
// blocks [9216, 11520): weights (4 tensors x 576 blocks)
__global__ __launch_bounds__(256)
void split_all_kernel(const float* __restrict__ q_in, const float* __restrict__ k_in,
                      const float* __restrict__ v_in,
                      const float* __restrict__ Wq, const float* __restrict__ Wk,
                      const float* __restrict__ Wv, const float* __restrict__ Wo,
                      __half* xq, __half* xk, __half* xvh, __half* xvl,
                      __half* wq, __half* wk, __half* wv,
                      __half* woh, __half* wol) {
    int blk = blockIdx.x;
    if (blk < 9216) {
        int z = blk / 3072;
        int i = (blk % 3072) * 256 + threadIdx.x;
        const float* s = z == 0 ? q_in : z == 1 ? k_in : v_in;
        float4 v = ((const float4*)s)[i];
        if (z < 2) {
            __half* d = z == 0 ? xq : xk;
            uint2 o = {packh(v.x, v.y), packh(v.z, v.w)};
            ((uint2*)d)[i] = o;
        } else {
            uint32_t h0 = packh(v.x, v.y), h1 = packh(v.z, v.w);
            __half2 a = *(__half2*)&h0, b = *(__half2*)&h1;
            uint32_t l0 = packh(v.x - __half2float(a.x), v.y - __half2float(a.y));
            uint32_t l1 = packh(v.z - __half2float(b.x), v.w - __half2float(b.y));
            uint2 hh = {h0, h1}, ll = {l0, l1};
            ((uint2*)xvh)[i] = hh;
            ((uint2*)xvl)[i] = ll;
        }
    } else {
        int wb = blk - 9216;
        int z = wb / 576;
        int i = (wb % 576) * 256 + threadIdx.x;
        const float* s = z == 0 ? Wq : z == 1 ? Wk : z == 2 ? Wv : Wo;
        float4 v = ((const float4*)s)[i];
        if (z < 3) {
            __half* d = z == 0 ? wq : z == 1 ? wk : wv;
            uint2 o = {packh(v.x, v.y), packh(v.z, v.w)};
            ((uint2*)d)[i] = o;
        } else {
            uint32_t h0 = packh(v.x, v.y), h1 = packh(v.z, v.w);
            __half2 a = *(__half2*)&h0, b = *(__half2*)&h1;
            uint32_t l0 = packh(v.x - __half2float(a.x), v.y - __half2float(a.y));
            uint32_t l1 = packh(v.z - __half2float(b.x), v.w - __half2float(b.y));
            uint2 hh = {h0, h1}, ll = {l0, l1};
            ((uint2*)woh)[i] = hh;
            ((uint2*)wol)[i] = ll;
        }
    }
}

// ====================== QKV projection (64x64 warp tiles) ===================
#define PTILE 10240            // 128 rows x 80 B
#define PSTG  30720            // A | Alo | W
#define PSMEM (3 * PSTG)       // 92160

__device__ __forceinline__ void qkv_issue(
    uint32_t stg, const __half* a, const __half* alo, const __half* w,
    int row0, int col0, int k0, int tid, int has_lo) {
#pragma unroll
    for (int j = 0; j < 4; j++) {
        int idx = tid + j * 128;
        int r = idx >> 2, ch = idx & 3;
        uint32_t doff = (uint32_t)(r * 80 + ch * 16);
        size_t ga = (size_t)(row0 + r) * DIMC + k0 + ch * 8;
        size_t gw = (size_t)(col0 + r) * DIMC + k0 + ch * 8;
        cp16(stg + doff,             a + ga);
        cp16(stg + 2 * PTILE + doff, w + gw);
        if (has_lo) cp16(stg + PTILE + doff, alo + ga);
    }
}

__global__ __launch_bounds__(128, 2)
void proj_qkv_kernel(
    const __half* __restrict__ xq, const __half* __restrict__ xk,
    const __half* __restrict__ xvh, const __half* __restrict__ xvl,
    const __half* __restrict__ wq, const __half* __restrict__ wk,
    const __half* __restrict__ wv,
    const float* __restrict__ bq, const float* __restrict__ bk,
    const float* __restrict__ bv,
    __half* __restrict__ oq, __half* __restrict__ ok, __half* __restrict__ ov) {
    extern __shared__ __align__(16) char dsm[];
    const uint32_t sb = smem_u32(dsm);
    const int tid = threadIdx.x;
    const int wid = tid >> 5;
    const int lane = tid & 31;
    const int wm = wid >> 1;
    const int wn = wid & 1;
    const int row0 = blockIdx.x * 128;
    const int col0 = blockIdx.y * 128;
    const int z = blockIdx.z;
    const int has_lo = (z == 2);
    const float oscale = (z == 0) ? QSCALE : 1.f;

    const __half* a  = z == 0 ? xq : z == 1 ? xk : xvh;
    const __half* w  = z == 0 ? wq : z == 1 ? wk : wv;
    const float* bias = z == 0 ? bq : z == 1 ? bk : bv;
    __half* op = z == 0 ? oq : z == 1 ? ok : ov;

    float bias_r[8][2];
#pragma unroll
    for (int j = 0; j < 8; j++) {
        int c = col0 + wn * 64 + j * 8 + (lane & 3) * 2;
        float2 bv2 = *(const float2*)&bias[c];
        bias_r[j][0] = bv2.x;
        bias_r[j][1] = bv2.y;
    }

    float acc[4][8][4];
#pragma unroll
    for (int i = 0; i < 4; i++)
#pragma unroll
        for (int j = 0; j < 8; j++)
#pragma unroll
            for (int k = 0; k < 4; k++) acc[i][j][k] = 0.f;

    const int lrow = (lane & 7) + (lane & 8);
    const int lcb = (lane >> 4) * 16;

    qkv_issue(sb, a, xvl, w, row0, col0, 0, tid, has_lo);
    CP_COMMIT();
    qkv_issue(sb + PSTG, a, xvl, w, row0, col0, 32, tid, has_lo);
    CP_COMMIT();

    for (int kt = 0; kt < 24; kt++) {
        if (kt < 23) { CP_WAIT1(); } else { CP_WAIT0(); }
        __syncthreads();
        if (kt < 22) {
            qkv_issue(sb + ((kt + 2) % 3) * PSTG, a, xvl, w, row0, col0, (kt + 2) * 32, tid, has_lo);
            CP_COMMIT();
        }
        const uint32_t stg = sb + (kt % 3) * PSTG;
#pragma unroll
        for (int ks = 0; ks < 2; ks++) {
            const uint32_t kb = (uint32_t)(ks * 32 + lcb);
            uint32_t af[4][4], alf[4][4];
#pragma unroll
            for (int i = 0; i < 4; i++) {
                uint32_t off = (uint32_t)((wm * 64 + i * 16 + lrow) * 80) + kb;
                ldm4(af[i], stg + off);
                if (has_lo) ldm4(alf[i], stg + PTILE + off);
            }
#pragma unroll
            for (int g = 0; g < 4; g++) {
                uint32_t off = (uint32_t)((wn * 64 + g * 16 + lrow) * 80) + kb;
                uint32_t b4[4];
                ldm4(b4, stg + 2 * PTILE + off);
#pragma unroll
                for (int i = 0; i < 4; i++) {
                    mma_f16(acc[i][2 * g],     af[i], b4[0], b4[2]);
                    mma_f16(acc[i][2 * g + 1], af[i], b4[1], b4[3]);
                    if (has_lo) {
                        mma_f16(acc[i][2 * g],     alf[i], b4[0], b4[2]);
                        mma_f16(acc[i][2 * g + 1], alf[i], b4[1], b4[3]);
                    }
                }
            }
        }
    }

#pragma unroll
    for (int i = 0; i < 4; i++) {
        const int m0 = row0 + wm * 64 + i * 16 + (lane >> 2);
#pragma unroll
        for (int j = 0; j < 8; j++) {
            const int c = col0 + wn * 64 + j * 8 + (lane & 3) * 2;
            const int h = c >> 6, d = c & 63;
            float v0 = (acc[i][j][0] + bias_r[j][0]) * oscale;
            float v1 = (acc[i][j][1] + bias_r[j][1]) * oscale;
            float v2 = (acc[i][j][2] + bias_r[j][0]) * oscale;
            float v3 = (acc[i][j][3] + bias_r[j][1]) * oscale;
            {
                const int gr = m0, b = gr >> 11, t = gr & 2047;
                size_t oi = (((size_t)b * NH + h) * TLEN + t) * HD + d;
                *(uint32_t*)&op[oi] = packh(v0, v1);
            }
            {
                const int gr = m0 + 8, b = gr >> 11, t = gr & 2047;
                size_t oi = (((size_t)b * NH + h) * TLEN + t) * HD + d;
                *(uint32_t*)&op[oi] = packh(v2, v3);
            }
        }
    }
}

// ====================== O projection (fp16, 2 MMA, occ 2) ===================
#define OTILE 10240
#define OSTG  30720            // A | Wh | Wl
#define OSMEM (3 * OSTG)       // 92160

__device__ __forceinline__ void o_issue(
    uint32_t stg, const __half* a, const __half* wh, const __half* wl,
    int row0, int col0, int k0, int tid) {
#pragma unroll
    for (int j = 0; j < 2; j++) {
        int idx = tid + j * 256;
        int r = idx >> 2, ch = idx & 3;
        uint32_t doff = (uint32_t)(r * 80 + ch * 16);
        size_t ga = (size_t)(row0 + r) * DIMC + k0 + ch * 8;
        size_t gw = (size_t)(col0 + r) * DIMC + k0 + ch * 8;
        cp16(stg + doff,             a + ga);
        cp16(stg + OTILE + doff,     wh + gw);
        cp16(stg + 2 * OTILE + doff, wl + gw);
    }
}

__global__ __launch_bounds__(256, 2)
void proj_o_kernel(const __half* __restrict__ a,
                   const __half* __restrict__ wh, const __half* __restrict__ wl,
                   const float* __restrict__ bias, float* __restrict__ out) {
    extern __shared__ __align__(16) char dsm[];
    const uint32_t sb = smem_u32(dsm);
    const int tid = threadIdx.x;
    const int wid = tid >> 5;
    const int lane = tid & 31;
    const int wm = wid >> 2;
    const int wn = wid & 3;
    const int row0 = blockIdx.x * 128;
    const int col0 = blockIdx.y * 128;

    float bias_r[4][2];
#pragma unroll
    for (int j = 0; j < 4; j++) {
        int c = col0 + wn * 32 + j * 8 + (lane & 3) * 2;
        float2 bv = *(const float2*)&bias[c];
        bias_r[j][0] = bv.x;
        bias_r[j][1] = bv.y;
    }

    float acc[4][4][4];
#pragma unroll
    for (int i = 0; i < 4; i++)
#pragma unroll
        for (int j = 0; j < 4; j++)
#pragma unroll
            for (int k = 0; k < 4; k++) acc[i][j][k] = 0.f;

    const int lrow = (lane & 7) + (lane & 8);
    const int lcb = (lane >> 4) * 16;

    o_issue(sb, a, wh, wl, row0, col0, 0, tid);
    CP_COMMIT();
    o_issue(sb + OSTG, a, wh, wl, row0, col0, 32, tid);
    CP_COMMIT();

    for (int kt = 0; kt < 24; kt++) {
        if (kt < 23) { CP_WAIT1(); } else { CP_WAIT0(); }
        __syncthreads();
        if (kt < 22) {
            o_issue(sb + ((kt + 2) % 3) * OSTG, a, wh, wl, row0, col0, (kt + 2) * 32, tid);
            CP_COMMIT();
        }
        const uint32_t stg = sb + (kt % 3) * OSTG;
#pragma unroll
        for (int ks = 0; ks < 2; ks++) {
            const uint32_t kb = (uint32_t)(ks * 32 + lcb);
            uint32_t af[4][4];
#pragma unroll
            for (int i = 0; i < 4; i++) {
                uint32_t off = (uint32_t)((wm * 64 + i * 16 + lrow) * 80) + kb;
                ldm4(af[i], stg + off);
            }
#pragma unroll
            for (int g = 0; g < 2; g++) {
                uint32_t off = (uint32_t)((wn * 32 + g * 16 + lrow) * 80) + kb;
                uint32_t bh4[4], bl4[4];
                ldm4(bh4, stg + OTILE + off);
                ldm4(bl4, stg + 2 * OTILE + off);
#pragma unroll
                for (int i = 0; i < 4; i++) {
                    mma_f16(acc[i][2 * g],     af[i], bh4[0], bh4[2]);
                    mma_f16(acc[i][2 * g],     af[i], bl4[0], bl4[2]);
                    mma_f16(acc[i][2 * g + 1], af[i], bh4[1], bh4[3]);
                    mma_f16(acc[i][2 * g + 1], af[i], bl4[1], bl4[3]);
                }
            }
        }
    }

#pragma unroll
    for (int i = 0; i < 4; i++) {
        const int m0 = row0 + wm * 64 + i * 16 + (lane >> 2);
#pragma unroll
        for (int j = 0; j < 4; j++) {
            const int c = col0 + wn * 32 + j * 8 + (lane & 3) * 2;
            float2 r01 = {acc[i][j][0] + bias_r[j][0], acc[i][j][1] + bias_r[j][1]};
            float2 r23 = {acc[i][j][2] + bias_r[j][0], acc[i][j][3] + bias_r[j][1]};
            *(float2*)&out[(size_t)m0 * DIMC + c] = r01;
            *(float2*)&out[(size_t)(m0 + 8) * DIMC + c] = r23;
        }
    }
}

// ====================== attention: 128q CTA, 32 rows/warp, 4-stage ==========
#define ATILE 8192
#define ASTG  16384
#define AT_SMEM (4 * ASTG)     // 65536

__device__ __forceinline__ void attn_issue_tile(
    uint32_t tilebase, const __half* src, int tid) {
#pragma unroll
    for (int j = 0; j < 4; j++) {
        int idx = tid + j * 128;
        int r = idx >> 3, ch = idx & 7;
        cp16(tilebase + SW128(r * 128 + ch * 16), src + (size_t)r * HD + ch * 8);
    }
}

__global__ __launch_bounds__(128, 2)
void attn_kernel(const __half* __restrict__ q, const __half* __restrict__ k,
                 const __half* __restrict__ v, __half* __restrict__ o) {
    extern __shared__ __align__(16) char dsm[];
    const uint32_t sb = smem_u32(dsm);
    const int tid = threadIdx.x;
    const int w = tid >> 5;
    const int lane = tid & 31;
    const int bh = blockIdx.y;
    const int q0 = blockIdx.x * 128;

    const __half* Q = q + ((size_t)bh * TLEN + q0) * HD;
    const __half* K = k + (size_t)bh * TLEN * HD;
    const __half* V = v + (size_t)bh * TLEN * HD;

    // stage Q (128 rows) into stage0+stage1 region, extract fragments
#pragma unroll
    for (int j = 0; j < 8; j++) {
        int idx = tid + j * 128;
        int r = idx >> 3, ch = idx & 7;
        cp16(sb + SW128(r * 128 + ch * 16), Q + (size_t)r * HD + ch * 8);
    }
    CP_COMMIT();
    CP_WAIT0();
    __syncthreads();

    const int lrow = (lane & 7) + (lane & 8);
    const int lcb = (lane >> 4) * 16;
    uint32_t qa[2][4][4];
#pragma unroll
    for (int rb = 0; rb < 2; rb++)
#pragma unroll
        for (int ks = 0; ks < 4; ks++) {
            uint32_t so = SW128((w * 32 + rb * 16 + lrow) * 128 + ks * 32 + lcb);
            ldm4(qa[rb][ks], sb + so);
        }
    __syncthreads();

    // prologue: KV tiles 0,1,2
#pragma unroll
    for (int s = 0; s < 3; s++) {
        attn_issue_tile(sb + s * ASTG,         K + (size_t)s * 64 * HD, tid);
        attn_issue_tile(sb + s * ASTG + ATILE, V + (size_t)s * 64 * HD, tid);
        CP_COMMIT();
    }

    float oacc[2][8][4];
#pragma unroll
    for (int rb = 0; rb < 2; rb++)
#pragma unroll
        for (int j = 0; j < 8; j++)
#pragma unroll
            for (int kk = 0; kk < 4; kk++) oacc[rb][j][kk] = 0.f;
    float lsum[2][2] = {{0.f, 0.f}, {0.f, 0.f}};

    for (int t = 0; t < 32; t++) {
        if (t < 30) { CP_WAIT2(); }
        else if (t == 30) { CP_WAIT1(); }
        else { CP_WAIT0(); }
        __syncthreads();
        if (t < 29) {
            const uint32_t ib = sb + ((t + 3) & 3) * ASTG;
            attn_issue_tile(ib,         K + (size_t)(t + 3) * 64 * HD, tid);
            attn_issue_tile(ib + ATILE, V + (size_t)(t + 3) * 64 * HD, tid);
            CP_COMMIT();
        }
        const uint32_t cK = sb + (t & 3) * ASTG;
        const uint32_t cV = cK + ATILE;

        // S = Q K^T : 32 x 64 per warp
        float sc[2][8][4];
#pragma unroll
        for (int rb = 0; rb < 2; rb++)
#pragma unroll
            for (int j = 0; j < 8; j++)
#pragma unroll
                for (int kk = 0; kk < 4; kk++) sc[rb][j][kk] = 0.f;
#pragma unroll
        for (int ks = 0; ks < 4; ks++) {
            const uint32_t kb = (uint32_t)(ks * 32 + lcb);
#pragma unroll
            for (int g = 0; g < 4; g++) {
                uint32_t so = SW128((g * 16 + lrow) * 128 + kb);
                uint32_t b4[4];
                ldm4(b4, cK + so);
#pragma unroll
                for (int rb = 0; rb < 2; rb++) {
                    mma_f16(sc[rb][2 * g],     qa[rb][ks], b4[0], b4[2]);
                    mma_f16(sc[rb][2 * g + 1], qa[rb][ks], b4[1], b4[3]);
                }
            }
        }

        // p = exp2(s~); pack fp16
        uint32_t ph[2][8][2];
#pragma unroll
        for (int rb = 0; rb < 2; rb++) {
            float p0 = 0.f, p1 = 0.f;
#pragma unroll
            for (int j = 0; j < 8; j++) {
                float e0 = ex2f(sc[rb][j][0]);
                float e1 = ex2f(sc[rb][j][1]);
                float e2 = ex2f(sc[rb][j][2]);
                float e3 = ex2f(sc[rb][j][3]);
                p0 += e0 + e1;
                p1 += e2 + e3;
                ph[rb][j][0] = packh(e0, e1);
                ph[rb][j][1] = packh(e2, e3);
            }
            lsum[rb][0] += p0;
            lsum[rb][1] += p1;
        }

        // O += P V
#pragma unroll
        for (int ks2 = 0; ks2 < 4; ks2++) {
            uint32_t pa[2][4];
#pragma unroll
            for (int rb = 0; rb < 2; rb++) {
                pa[rb][0] = ph[rb][2 * ks2][0];
                pa[rb][1] = ph[rb][2 * ks2][1];
                pa[rb][2] = ph[rb][2 * ks2 + 1][0];
                pa[rb][3] = ph[rb][2 * ks2 + 1][1];
            }
#pragma unroll
            for (int g = 0; g < 4; g++) {
                uint32_t so = SW128((ks2 * 16 + lrow) * 128 + g * 32 + lcb);
                uint32_t vf[4];
                ldm4t(vf, cV + so);
#pragma unroll
                for (int rb = 0; rb < 2; rb++) {
                    mma_f16(oacc[rb][2 * g],     pa[rb], vf[0], vf[1]);
                    mma_f16(oacc[rb][2 * g + 1], pa[rb], vf[2], vf[3]);
                }
            }
        }
    }

    const int b = bh / NH, h = bh % NH;
#pragma unroll
    for (int rb = 0; rb < 2; rb++) {
        float l0 = lsum[rb][0], l1 = lsum[rb][1];
        l0 += __shfl_xor_sync(0xffffffffu, l0, 1);
        l0 += __shfl_xor_sync(0xffffffffu, l0, 2);
        l1 += __shfl_xor_sync(0xffffffffu, l1, 1);
        l1 += __shfl_xor_sync(0xffffffffu, l1, 2);
        const float inv0 = 1.f / l0;
        const float inv1 = 1.f / l1;
        const int qr0 = q0 + w * 32 + rb * 16 + (lane >> 2);
        const int qr1 = qr0 + 8;
        size_t base0 = ((size_t)b * TLEN + qr0) * DIMC + h * HD + (lane & 3) * 2;
        size_t base1 = ((size_t)b * TLEN + qr1) * DIMC + h * HD + (lane & 3) * 2;
#pragma unroll
        for (int g = 0; g < 8; g++) {
            *(uint32_t*)&o[base0 + g * 8] = packh(oacc[rb][g][0] * inv0, oacc[rb][g][1] * inv0);
            *(uint32_t*)&o[base1 + g * 8] = packh(oacc[rb][g][2] * inv1, oacc[rb][g][3] * inv1);
        }
    }
}

// ====================== launch ==============================================
extern "C" void kernel_launch(void* const* d_in, const int* in_sizes, int n_in,
                              void* d_out, int out_size) {
    const float* q_in = (const float*)d_in[0];
    const float* k_in = (const float*)d_in[1];
    const float* v_in = (const float*)d_in[2];
    const float* Wq = (const float*)d_in[3];
    const float* bq = (const float*)d_in[4];
    const float* Wk = (const float*)d_in[5];
    const float* bk = (const float*)d_in[6];
    const float* Wv = (const float*)d_in[7];
    const float* bv = (const float*)d_in[8];
    const float* Wo = (const float*)d_in[9];
    const float* bo = (const float*)d_in[10];
    float* out = (float*)d_out;

    __half *xq, *xk, *xvh, *xvl, *wq, *wk, *wv, *woh, *wol, *pq, *pk, *pv, *pa;
    cudaGetSymbolAddress((void**)&xq, g_xq);
    cudaGetSymbolAddress((void**)&xk, g_xk);
    cudaGetSymbolAddress((void**)&xvh, g_xv_h);
    cudaGetSymbolAddress((void**)&xvl, g_xv_l);
    cudaGetSymbolAddress((void**)&wq, g_wq);
    cudaGetSymbolAddress((void**)&wk, g_wk);
    cudaGetSymbolAddress((void**)&wv, g_wv);
    cudaGetSymbolAddress((void**)&woh, g_wo_h);
    cudaGetSymbolAddress((void**)&wol, g_wo_l);
    cudaGetSymbolAddress((void**)&pq, g_q);
    cudaGetSymbolAddress((void**)&pk, g_k);
    cudaGetSymbolAddress((void**)&pv, g_v);
    cudaGetSymbolAddress((void**)&pa, g_a);

    cudaFuncSetAttribute(proj_qkv_kernel, cudaFuncAttributeMaxDynamicSharedMemorySize, PSMEM);
    cudaFuncSetAttribute(proj_o_kernel, cudaFuncAttributeMaxDynamicSharedMemorySize, OSMEM);
    cudaFuncSetAttribute(attn_kernel, cudaFuncAttributeMaxDynamicSharedMemorySize, AT_SMEM);

    split_all_kernel<<<11520, 256>>>(q_in, k_in, v_in, Wq, Wk, Wv, Wo,
                                     xq, xk, xvh, xvl, wq, wk, wv, woh, wol);

    dim3 pgrid(MROWS / 128, DIMC / 128, 3);   // 32 x 6 x 3
    proj_qkv_kernel<<<pgrid, 128, PSMEM>>>(xq, xk, xvh, xvl, wq, wk, wv,
                                           bq, bk, bv, pq, pk, pv);

    dim3 agrid(TLEN / 128, BSZ * NH);          // 16 x 24
    attn_kernel<<<agrid, 128, AT_SMEM>>>(pq, pk, pv, pa);

    dim3 ogrid(MROWS / 128, DIMC / 128);
    proj_o_kernel<<<ogrid, 256, OSMEM>>>(pa, woh, wol, bo, out);
}